// round 10
// baseline (speedup 1.0000x reference)
#include <cuda_runtime.h>
#include <math.h>
#include <stdint.h>

constexpr int H    = 128;
constexpr int B    = 512;
constexpr int T    = 128;
constexpr int S    = 1536;   // 3 inputs * B
constexpr int NB   = 12;     // seqs per block
constexpr int NBLK = 128;
constexpr int NTH  = 512;

constexpr int HPW  = 132;    // padded h row
constexpr int HOFF = 68;
constexpr int ACTW = 528;

// smem weight cache: 22 of 32 k4-chunks resident (11 per lane-parity)
constexpr int NW   = 22;
constexpr int NWH  = 11;
constexpr int WS_FLOATS = NW * 2048;                 // 22 chunks x 512 float4
constexpr int SM_HP   = WS_FLOATS;                   // hp offset (floats)
constexpr int SM_ACT  = SM_HP + NB * HPW;
constexpr int SM_XPS  = SM_ACT + NB * ACTW;
constexpr int SMEM_FLOATS = SM_XPS + 64;
constexpr int SMEM_BYTES  = SMEM_FLOATS * 4;         // ~212 KB

// k4-major packed weights: g_W[k4*512 + j] = {W[j][4k4..4k4+3]}
__device__ float4 g_W1h[32 * 512];
__device__ float4 g_W2i[32 * 512];
__device__ float4 g_W2h[32 * 512];
__device__ float  g_b1[512];
__device__ float  g_b2[512];
__device__ float  g_wx1[5 * 512];
__device__ float  g_out1[(size_t)S * T * H];
__device__ float  g_xpre[(size_t)S * T * 512];
__device__ float  g_lasth[S * H];
__device__ float  g_ps1[S * H];
__device__ float  g_pq1[S * H];
__device__ float  g_ps2[S * H];
__device__ float  g_pq2[S * H];
__device__ float2 g_bn1[3 * H];
__device__ float2 g_bn2[3 * H];

typedef unsigned long long ull;

__device__ __forceinline__ ull pk2(float x, float y) {
    ull r;
    asm("mov.b64 %0, {%1,%2};" : "=l"(r) : "r"(__float_as_uint(x)), "r"(__float_as_uint(y)));
    return r;
}
__device__ __forceinline__ float2 upk2(ull v) {
    unsigned lo, hi;
    asm("mov.b64 {%0,%1}, %2;" : "=r"(lo), "=r"(hi) : "l"(v));
    return make_float2(__uint_as_float(lo), __uint_as_float(hi));
}
__device__ __forceinline__ ull ffma2(ull a, ull b, ull c) {
    ull d;
    asm("fma.rn.f32x2 %0, %1, %2, %3;" : "=l"(d) : "l"(a), "l"(b), "l"(c));
    return d;
}
__device__ __forceinline__ float sigm(float x) {
    return __fdividef(1.f, 1.f + __expf(-x));
}

// ---------- pack weights ----------
__global__ void prep_kernel(const float* Wih1, const float* Whh1, const float* bih1, const float* bhh1,
                            const float* Wih2, const float* Whh2, const float* bih2, const float* bhh2) {
    int tid = blockIdx.x * blockDim.x + threadIdx.x;
    int stride = gridDim.x * blockDim.x;
    for (int idx = tid; idx < 32 * 512; idx += stride) {
        int k4 = idx >> 9, j = idx & 511;
        g_W1h[idx] = *(const float4*)&Whh1[j * H + 4 * k4];
        g_W2i[idx] = *(const float4*)&Wih2[j * H + 4 * k4];
        g_W2h[idx] = *(const float4*)&Whh2[j * H + 4 * k4];
    }
    for (int j = tid; j < 512; j += stride) {
        g_b1[j] = bih1[j] + bhh1[j];
        g_b2[j] = bih2[j] + bhh2[j];
        for (int d = 0; d < 5; d++) g_wx1[d * 512 + j] = Wih1[j * 5 + d];
    }
}

// cooperative copy of 22 chunks into smem: chunk c<11 -> k4=c (even lanes), c>=11 -> k4=c+5 (odd lanes)
__device__ __forceinline__ void fill_ws(float* ws, const float4* W, int tid) {
    float4* wsv = (float4*)ws;
    for (int i = tid; i < NW * 512; i += NTH) {
        int c = i >> 9, j = i & 511;
        int k4 = (c < NWH) ? c : (c + 5);
        wsv[i] = W[(k4 << 9) + j];
    }
}

// ---------- layer 1 LSTM ----------
__global__ void __launch_bounds__(NTH, 1)
lstm1_kernel(const float* __restrict__ xa, const float* __restrict__ xp, const float* __restrict__ xn) {
    extern __shared__ __align__(16) float smem[];
    float* ws  = smem;
    float* hp  = smem + SM_HP;
    float* act = smem + SM_ACT;
    float* xps = smem + SM_XPS;          // [NB][5]

    const int tid = threadIdx.x;
    const int p   = tid >> 1;
    const int kh  = tid & 1;
    const int sbase = blockIdx.x * NB;

    const float biasA = kh ? 0.f : g_b1[p];
    const float biasB = kh ? 0.f : g_b1[p + 256];
    float wxA[3], wxB[3];
    const int nd = kh ? 2 : 3;
    const int d0 = kh ? 3 : 0;
#pragma unroll
    for (int d = 0; d < 3; d++) {
        int dd = d0 + d;
        wxA[d] = (d < nd) ? g_wx1[dd * 512 + p]       : 0.f;
        wxB[d] = (d < nd) ? g_wx1[dd * 512 + p + 256] : 0.f;
    }

    const bool ktanh = kh && (p < 128);
    const float zmul = ktanh ? 2.f : 1.f;
    const float amul = ktanh ? 2.f : 1.f;
    const float aadd = ktanh ? -1.f : 0.f;
    const int  acol  = kh ? (p + 272) : p;

    const int m  = tid & 127;
    const int cm = m + ((m >> 6) << 2);
    const int sb = tid >> 7;
    float csr[3] = {0,0,0}, sum[3] = {0,0,0}, sq[3] = {0,0,0};

    const float* xptr = xa; int xoff = 0, xsl = 0, xd = 0;
    const bool is_loader = (tid < NB * 5);
    if (is_loader) {
        xsl = tid / 5; xd = tid - 5 * xsl;
        int s = sbase + xsl, in = s >> 9, b = s & 511;
        xptr = (in == 0) ? xa : ((in == 1) ? xp : xn);
        xoff = b * (T * 5) + xd;
    }
    fill_ws(ws, g_W1h, tid);
    for (int i = tid; i < NB * HPW; i += NTH) hp[i] = 0.f;
    if (is_loader) xps[xsl * 5 + xd] = __ldg(&xptr[xoff]);
    __syncthreads();

    const float4* WbG = g_W1h + (kh ? (16 << 9) : 0);
    const int woff   = kh ? (NWH * 2048) : 0;
    const int hbase0 = kh ? HOFF : 0;

    for (int t = 0; t < T; t++) {
        float xnv = 0.f;
        if (is_loader && t + 1 < T) xnv = __ldg(&xptr[xoff + (t + 1) * 5]);

        ull accA[NB], accB[NB];
#pragma unroll
        for (int s = 0; s < NB; s++) {
            float dA = biasA, dB = biasB;
#pragma unroll
            for (int d = 0; d < 3; d++) {
                float xv = (d < nd) ? xps[s * 5 + d0 + d] : 0.f;
                dA = fmaf(wxA[d], xv, dA);
                dB = fmaf(wxB[d], xv, dB);
            }
            accA[s] = pk2(dA, 0.f);
            accB[s] = pk2(dB, 0.f);
        }

        // prefetch global tail (kk = 11..15)
        float4 wAc = __ldg(WbG + (NWH << 9) + p);
        float4 wBc = __ldg(WbG + (NWH << 9) + p + 256);

        // smem-resident chunks
#pragma unroll
        for (int kk = 0; kk < NWH; kk++) {
            float4 wA = *(const float4*)&ws[woff + kk * 2048 + 4 * p];
            float4 wB = *(const float4*)&ws[woff + kk * 2048 + 4 * (p + 256)];
            ull wAlo = pk2(wA.x, wA.y), wAhi = pk2(wA.z, wA.w);
            ull wBlo = pk2(wB.x, wB.y), wBhi = pk2(wB.z, wB.w);
            const float* hrow = hp + hbase0 + 4 * kk;
#pragma unroll
            for (int s = 0; s < NB; s++) {
                ulonglong2 hv = *(const ulonglong2*)&hrow[s * HPW];
                accA[s] = ffma2(wAlo, hv.x, accA[s]);
                accA[s] = ffma2(wAhi, hv.y, accA[s]);
                accB[s] = ffma2(wBlo, hv.x, accB[s]);
                accB[s] = ffma2(wBhi, hv.y, accB[s]);
            }
        }
        // global tail
#pragma unroll
        for (int kk = NWH; kk < 16; kk++) {
            float4 wAn, wBn;
            if (kk + 1 < 16) {
                wAn = __ldg(WbG + ((kk + 1) << 9) + p);
                wBn = __ldg(WbG + ((kk + 1) << 9) + p + 256);
            }
            ull wAlo = pk2(wAc.x, wAc.y), wAhi = pk2(wAc.z, wAc.w);
            ull wBlo = pk2(wBc.x, wBc.y), wBhi = pk2(wBc.z, wBc.w);
            const float* hrow = hp + hbase0 + 4 * kk;
#pragma unroll
            for (int s = 0; s < NB; s++) {
                ulonglong2 hv = *(const ulonglong2*)&hrow[s * HPW];
                accA[s] = ffma2(wAlo, hv.x, accA[s]);
                accA[s] = ffma2(wAhi, hv.y, accA[s]);
                accB[s] = ffma2(wBlo, hv.x, accB[s]);
                accB[s] = ffma2(wBhi, hv.y, accB[s]);
            }
            if (kk + 1 < 16) { wAc = wAn; wBc = wBn; }
        }

#pragma unroll
        for (int s = 0; s < NB; s++) {
            float2 vA = upk2(accA[s]); float zA = vA.x + vA.y;
            float2 vB = upk2(accB[s]); float zB = vB.x + vB.y;
            zA += __shfl_xor_sync(0xffffffffu, zA, 1);
            zB += __shfl_xor_sync(0xffffffffu, zB, 1);
            float z = kh ? zB : zA;
            float sg = sigm(z * zmul);
            act[s * ACTW + acol] = fmaf(sg, amul, aadd);
        }
        __syncthreads();

        if (is_loader && t + 1 < T) xps[xsl * 5 + xd] = xnv;
#pragma unroll
        for (int r = 0; r < 3; r++) {
            int s = sb + 4 * r;
            const float* arow = act + s * ACTW;
            float gi = arow[m], gf = arow[m + 128], gg = arow[m + 272], go = arow[m + 400];
            float c = fmaf(gf, csr[r], gi * gg);
            csr[r] = c;
            float th = fmaf(2.f, sigm(2.f * c), -1.f);
            float h = go * th;
            hp[s * HPW + cm] = h;
            g_out1[((size_t)(sbase + s) * T + t) * H + m] = h;
            sum[r] += h;
            sq[r] = fmaf(h, h, sq[r]);
        }
        __syncthreads();
    }
#pragma unroll
    for (int r = 0; r < 3; r++) {
        int idx = (sbase + sb + 4 * r) * H + m;
        g_ps1[idx] = sum[r];
        g_pq1[idx] = sq[r];
    }
}

// ---------- BN stats reduce ----------
__global__ void __launch_bounds__(128)
bn_reduce_kernel(const float* __restrict__ ps, const float* __restrict__ pq,
                 const float* __restrict__ gamma, const float* __restrict__ beta,
                 float2* __restrict__ bnout) {
    __shared__ double rs[128], rq[128];
    int cidx = blockIdx.x;
    int in = cidx >> 7, c = cidx & 127;
    int t = threadIdx.x;
    double s = 0.0, q = 0.0;
    for (int b = t; b < B; b += 128) {
        int idx = (in * B + b) * H + c;
        s += (double)ps[idx];
        q += (double)pq[idx];
    }
    rs[t] = s; rq[t] = q;
    __syncthreads();
    for (int off = 64; off > 0; off >>= 1) {
        if (t < off) { rs[t] += rs[t + off]; rq[t] += rq[t + off]; }
        __syncthreads();
    }
    if (t == 0) {
        double n = (double)B * T;
        double mean = rs[0] / n;
        double var = rq[0] / n - mean * mean;
        float scale = gamma[c] * (float)rsqrt(var + 1e-5);
        float shift = beta[c] - (float)mean * scale;
        bnout[cidx] = make_float2(scale, shift);
    }
}

// ---------- xpre GEMM: 32 tokens x 512 gates per block ----------
__global__ void __launch_bounds__(512)
xpre_kernel() {
    __shared__ __align__(16) float xs[32][H];   // 16 KB
    const int tid = threadIdx.x;
    const int tok0 = blockIdx.x * 32;

#pragma unroll
    for (int it = 0; it < 2; it++) {
        int i = tid + it * 512;          // 0..1023 float4s
        int tl = i >> 5, f4 = i & 31;
        int tok = tok0 + tl;
        float4 v = __ldg(((const float4*)g_out1) + (size_t)tok * 32 + f4);
        int in = (tok >> 7) >> 9;
        int m0 = f4 * 4;
        float2 b0 = g_bn1[in * H + m0 + 0];
        float2 b1 = g_bn1[in * H + m0 + 1];
        float2 b2 = g_bn1[in * H + m0 + 2];
        float2 b3 = g_bn1[in * H + m0 + 3];
        xs[tl][m0 + 0] = fmaf(v.x, b0.x, b0.y);
        xs[tl][m0 + 1] = fmaf(v.y, b1.x, b1.y);
        xs[tl][m0 + 2] = fmaf(v.z, b2.x, b2.y);
        xs[tl][m0 + 3] = fmaf(v.w, b3.x, b3.y);
    }
    __syncthreads();

    ull acc[32];
#pragma unroll
    for (int tk = 0; tk < 32; tk++) acc[tk] = 0ull;

    float4 wc = __ldg(&g_W2i[tid]);
#pragma unroll 4
    for (int k4 = 0; k4 < 32; k4++) {
        float4 wn;
        if (k4 + 1 < 32) wn = __ldg(&g_W2i[((k4 + 1) << 9) + tid]);
        ull wlo = pk2(wc.x, wc.y), whi = pk2(wc.z, wc.w);
#pragma unroll
        for (int tk = 0; tk < 32; tk++) {
            ulonglong2 xv = *(const ulonglong2*)&xs[tk][4 * k4];
            acc[tk] = ffma2(wlo, xv.x, acc[tk]);
            acc[tk] = ffma2(whi, xv.y, acc[tk]);
        }
        if (k4 + 1 < 32) wc = wn;
    }
#pragma unroll
    for (int tk = 0; tk < 32; tk++) {
        float2 v = upk2(acc[tk]);
        g_xpre[(size_t)(tok0 + tk) * 512 + tid] = v.x + v.y;
    }
}

// ---------- layer 2 LSTM: recurrent part (Whh2), seed = bias + xpre ----------
__global__ void __launch_bounds__(NTH, 1)
lstm2_kernel() {
    extern __shared__ __align__(16) float smem[];
    float* ws  = smem;
    float* hp  = smem + SM_HP;
    float* act = smem + SM_ACT;

    const int tid = threadIdx.x;
    const int p   = tid >> 1;
    const int kh  = tid & 1;
    const int sbase = blockIdx.x * NB;

    const int myGate = p + (kh ? 256 : 0);
    const float bias = g_b2[myGate];

    const bool ktanh = kh && (p < 128);
    const float zmul = ktanh ? 2.f : 1.f;
    const float amul = ktanh ? 2.f : 1.f;
    const float aadd = ktanh ? -1.f : 0.f;
    const int  acol  = kh ? (p + 272) : p;

    const int m  = tid & 127;
    const int cm = m + ((m >> 6) << 2);
    const int sb = tid >> 7;
    float csr[3] = {0,0,0}, sum[3] = {0,0,0}, sq[3] = {0,0,0};

    fill_ws(ws, g_W2h, tid);
    for (int i = tid; i < NB * HPW; i += NTH) hp[i] = 0.f;
    __syncthreads();

    const float4* WbG = g_W2h + (kh ? (16 << 9) : 0);
    const int woff   = kh ? (NWH * 2048) : 0;
    const int hbase0 = kh ? HOFF : 0;

    for (int t = 0; t < T; t++) {
        float xv[NB];
#pragma unroll
        for (int s = 0; s < NB; s++)
            xv[s] = __ldg(&g_xpre[((size_t)(sbase + s) * T + t) * 512 + myGate]);

        ull accA[NB], accB[NB];
#pragma unroll
        for (int s = 0; s < NB; s++) { accA[s] = 0ull; accB[s] = 0ull; }

        float4 wAc = __ldg(WbG + (NWH << 9) + p);
        float4 wBc = __ldg(WbG + (NWH << 9) + p + 256);

#pragma unroll
        for (int kk = 0; kk < NWH; kk++) {
            float4 wA = *(const float4*)&ws[woff + kk * 2048 + 4 * p];
            float4 wB = *(const float4*)&ws[woff + kk * 2048 + 4 * (p + 256)];
            ull wAlo = pk2(wA.x, wA.y), wAhi = pk2(wA.z, wA.w);
            ull wBlo = pk2(wB.x, wB.y), wBhi = pk2(wB.z, wB.w);
            const float* hrow = hp + hbase0 + 4 * kk;
#pragma unroll
            for (int s = 0; s < NB; s++) {
                ulonglong2 hv = *(const ulonglong2*)&hrow[s * HPW];
                accA[s] = ffma2(wAlo, hv.x, accA[s]);
                accA[s] = ffma2(wAhi, hv.y, accA[s]);
                accB[s] = ffma2(wBlo, hv.x, accB[s]);
                accB[s] = ffma2(wBhi, hv.y, accB[s]);
            }
        }
#pragma unroll
        for (int kk = NWH; kk < 16; kk++) {
            float4 wAn, wBn;
            if (kk + 1 < 16) {
                wAn = __ldg(WbG + ((kk + 1) << 9) + p);
                wBn = __ldg(WbG + ((kk + 1) << 9) + p + 256);
            }
            ull wAlo = pk2(wAc.x, wAc.y), wAhi = pk2(wAc.z, wAc.w);
            ull wBlo = pk2(wBc.x, wBc.y), wBhi = pk2(wBc.z, wBc.w);
            const float* hrow = hp + hbase0 + 4 * kk;
#pragma unroll
            for (int s = 0; s < NB; s++) {
                ulonglong2 hv = *(const ulonglong2*)&hrow[s * HPW];
                accA[s] = ffma2(wAlo, hv.x, accA[s]);
                accA[s] = ffma2(wAhi, hv.y, accA[s]);
                accB[s] = ffma2(wBlo, hv.x, accB[s]);
                accB[s] = ffma2(wBhi, hv.y, accB[s]);
            }
            if (kk + 1 < 16) { wAc = wAn; wBc = wBn; }
        }

#pragma unroll
        for (int s = 0; s < NB; s++) {
            float2 vA = upk2(accA[s]); float zA = vA.x + vA.y;
            float2 vB = upk2(accB[s]); float zB = vB.x + vB.y;
            float seed = bias + xv[s];
            if (kh) zB += seed; else zA += seed;
            zA += __shfl_xor_sync(0xffffffffu, zA, 1);
            zB += __shfl_xor_sync(0xffffffffu, zB, 1);
            float z = kh ? zB : zA;
            float sg = sigm(z * zmul);
            act[s * ACTW + acol] = fmaf(sg, amul, aadd);
        }
        __syncthreads();

#pragma unroll
        for (int r = 0; r < 3; r++) {
            int s = sb + 4 * r;
            const float* arow = act + s * ACTW;
            float gi = arow[m], gf = arow[m + 128], gg = arow[m + 272], go = arow[m + 400];
            float c = fmaf(gf, csr[r], gi * gg);
            csr[r] = c;
            float th = fmaf(2.f, sigm(2.f * c), -1.f);
            float h = go * th;
            hp[s * HPW + cm] = h;
            sum[r] += h;
            sq[r] = fmaf(h, h, sq[r]);
            if (t == T - 1) g_lasth[(sbase + s) * H + m] = h;
        }
        __syncthreads();
    }
#pragma unroll
    for (int r = 0; r < 3; r++) {
        int idx = (sbase + sb + 4 * r) * H + m;
        g_ps2[idx] = sum[r];
        g_pq2[idx] = sq[r];
    }
}

// ---------- FC + L2 normalize ----------
__global__ void __launch_bounds__(128)
final_kernel(const float* __restrict__ fcW, const float* __restrict__ fcb, float* __restrict__ out) {
    __shared__ float xn[H];
    __shared__ float emb[H];
    __shared__ float red[128];
    int s = blockIdx.x, j = threadIdx.x;
    int in = s >> 9, b = s & 511;

    float2 bn = g_bn2[in * H + j];
    xn[j] = fmaf(g_lasth[s * H + j], bn.x, bn.y);
    __syncthreads();

    float e = fcb[j];
    const float* wrow = fcW + j * H;
#pragma unroll 4
    for (int k = 0; k < H; k++) e = fmaf(__ldg(&wrow[k]), xn[k], e);
    emb[j] = e;
    red[j] = e * e;
    __syncthreads();
    for (int off = 64; off > 0; off >>= 1) {
        if (j < off) red[j] += red[j + off];
        __syncthreads();
    }
    float norm = sqrtf(red[0]);
    float inv = 1.f / fmaxf(norm, 1e-12f);
    out[((size_t)in * B + b) * H + j] = emb[j] * inv;
}

extern "C" void kernel_launch(void* const* d_in, const int* in_sizes, int n_in,
                              void* d_out, int out_size) {
    const float* a    = (const float*)d_in[0];
    const float* p    = (const float*)d_in[1];
    const float* n    = (const float*)d_in[2];
    const float* Wih1 = (const float*)d_in[3];
    const float* Whh1 = (const float*)d_in[4];
    const float* bih1 = (const float*)d_in[5];
    const float* bhh1 = (const float*)d_in[6];
    const float* g1   = (const float*)d_in[7];
    const float* b1   = (const float*)d_in[8];
    const float* Wih2 = (const float*)d_in[9];
    const float* Whh2 = (const float*)d_in[10];
    const float* bih2 = (const float*)d_in[11];
    const float* bhh2 = (const float*)d_in[12];
    const float* g2   = (const float*)d_in[13];
    const float* b2   = (const float*)d_in[14];
    const float* fcW  = (const float*)d_in[15];
    const float* fcb  = (const float*)d_in[16];
    float* out = (float*)d_out;

    static int smem_set = 0;
    if (!smem_set) {
        cudaFuncSetAttribute(lstm1_kernel, cudaFuncAttributeMaxDynamicSharedMemorySize, SMEM_BYTES);
        cudaFuncSetAttribute(lstm2_kernel, cudaFuncAttributeMaxDynamicSharedMemorySize, SMEM_BYTES);
        smem_set = 1;
    }

    float2 *bn1p, *bn2p;
    cudaGetSymbolAddress((void**)&bn1p, g_bn1);
    cudaGetSymbolAddress((void**)&bn2p, g_bn2);
    float *ps1, *pq1, *ps2, *pq2;
    cudaGetSymbolAddress((void**)&ps1, g_ps1);
    cudaGetSymbolAddress((void**)&pq1, g_pq1);
    cudaGetSymbolAddress((void**)&ps2, g_ps2);
    cudaGetSymbolAddress((void**)&pq2, g_pq2);

    prep_kernel<<<64, 256>>>(Wih1, Whh1, bih1, bhh1, Wih2, Whh2, bih2, bhh2);
    lstm1_kernel<<<NBLK, NTH, SMEM_BYTES>>>(a, p, n);
    bn_reduce_kernel<<<3 * H, 128>>>(ps1, pq1, g1, b1, bn1p);
    xpre_kernel<<<(S * T) / 32, 512>>>();
    lstm2_kernel<<<NBLK, NTH, SMEM_BYTES>>>();
    bn_reduce_kernel<<<3 * H, 128>>>(ps2, pq2, g2, b2, bn2p);
    final_kernel<<<S, 128>>>(fcW, fcb, out);
}

// round 11
// speedup vs baseline: 1.0967x; 1.0967x over previous
#include <cuda_runtime.h>
#include <cuda_fp16.h>
#include <math.h>
#include <stdint.h>

constexpr int H    = 128;
constexpr int B    = 512;
constexpr int T    = 128;
constexpr int S    = 1536;   // 3 inputs * B
constexpr int NB   = 12;     // seqs per block
constexpr int NBLK = 128;
constexpr int NTH  = 512;

constexpr int HPW  = 132;    // padded h row
constexpr int HOFF = 68;
constexpr int ACTW = 528;

// fp16 packed weights: g_W16[k4*256 + p] = halves { W[p][4k4..+1] , W[p][4k4+2..+3],
//                                                   W[p+256][4k4..+1], W[p+256][4k4+2..+3] }
__device__ uint4  g_W1h16[32 * 256];
__device__ uint4  g_W2i16[32 * 256];
__device__ uint4  g_W2h16[32 * 256];
__device__ float  g_b1[512];
__device__ float  g_b2[512];
__device__ float  g_wx1[5 * 512];
__device__ float  g_out1[(size_t)S * T * H];
__device__ float  g_xpre[(size_t)S * T * 512];
__device__ float  g_lasth[S * H];
__device__ float  g_ps1[S * H];
__device__ float  g_pq1[S * H];
__device__ float  g_ps2[S * H];
__device__ float  g_pq2[S * H];
__device__ float2 g_bn1[3 * H];
__device__ float2 g_bn2[3 * H];

typedef unsigned long long ull;

__device__ __forceinline__ ull pk2(float x, float y) {
    ull r;
    asm("mov.b64 %0, {%1,%2};" : "=l"(r) : "r"(__float_as_uint(x)), "r"(__float_as_uint(y)));
    return r;
}
__device__ __forceinline__ float2 upk2(ull v) {
    unsigned lo, hi;
    asm("mov.b64 {%0,%1}, %2;" : "=r"(lo), "=r"(hi) : "l"(v));
    return make_float2(__uint_as_float(lo), __uint_as_float(hi));
}
__device__ __forceinline__ ull ffma2(ull a, ull b, ull c) {
    ull d;
    asm("fma.rn.f32x2 %0, %1, %2, %3;" : "=l"(d) : "l"(a), "l"(b), "l"(c));
    return d;
}
__device__ __forceinline__ float sigm(float x) {
    return __fdividef(1.f, 1.f + __expf(-x));
}
// unpack one uint (half2) -> packed f32x2 operand
__device__ __forceinline__ ull h2f2(unsigned v) {
    float2 f = __half22float2(*(const __half2*)&v);
    return pk2(f.x, f.y);
}

// ---------- pack fp16 weights ----------
__global__ void prep_kernel(const float* Wih1, const float* Whh1, const float* bih1, const float* bhh1,
                            const float* Wih2, const float* Whh2, const float* bih2, const float* bhh2) {
    int tid = blockIdx.x * blockDim.x + threadIdx.x;
    int stride = gridDim.x * blockDim.x;
    for (int idx = tid; idx < 32 * 256; idx += stride) {
        int k4 = idx >> 8, p = idx & 255;
        int jA = p, jB = p + 256, k0 = 4 * k4;
        uint4 v;
        __half2 h;
        const float* rA; const float* rB;

        rA = Whh1 + jA * H + k0; rB = Whh1 + jB * H + k0;
        h = __floats2half2_rn(rA[0], rA[1]); v.x = *(unsigned*)&h;
        h = __floats2half2_rn(rA[2], rA[3]); v.y = *(unsigned*)&h;
        h = __floats2half2_rn(rB[0], rB[1]); v.z = *(unsigned*)&h;
        h = __floats2half2_rn(rB[2], rB[3]); v.w = *(unsigned*)&h;
        g_W1h16[idx] = v;

        rA = Wih2 + jA * H + k0; rB = Wih2 + jB * H + k0;
        h = __floats2half2_rn(rA[0], rA[1]); v.x = *(unsigned*)&h;
        h = __floats2half2_rn(rA[2], rA[3]); v.y = *(unsigned*)&h;
        h = __floats2half2_rn(rB[0], rB[1]); v.z = *(unsigned*)&h;
        h = __floats2half2_rn(rB[2], rB[3]); v.w = *(unsigned*)&h;
        g_W2i16[idx] = v;

        rA = Whh2 + jA * H + k0; rB = Whh2 + jB * H + k0;
        h = __floats2half2_rn(rA[0], rA[1]); v.x = *(unsigned*)&h;
        h = __floats2half2_rn(rA[2], rA[3]); v.y = *(unsigned*)&h;
        h = __floats2half2_rn(rB[0], rB[1]); v.z = *(unsigned*)&h;
        h = __floats2half2_rn(rB[2], rB[3]); v.w = *(unsigned*)&h;
        g_W2h16[idx] = v;
    }
    for (int j = tid; j < 512; j += stride) {
        g_b1[j] = bih1[j] + bhh1[j];
        g_b2[j] = bih2[j] + bhh2[j];
        for (int d = 0; d < 5; d++) g_wx1[d * 512 + j] = Wih1[j * 5 + d];
    }
}

// ---------- layer 1 LSTM ----------
// thread = gate-pair p = tid>>1 (gates p, p+256) x k-half kh = tid&1 (lane parity)
__global__ void __launch_bounds__(NTH, 1)
lstm1_kernel(const float* __restrict__ xa, const float* __restrict__ xp, const float* __restrict__ xn) {
    __shared__ __align__(16) float hp[NB * HPW];
    __shared__ float act[NB * ACTW];
    __shared__ float xps[NB][5];

    const int tid = threadIdx.x;
    const int p   = tid >> 1;
    const int kh  = tid & 1;
    const int sbase = blockIdx.x * NB;

    const float biasA = kh ? 0.f : g_b1[p];
    const float biasB = kh ? 0.f : g_b1[p + 256];
    float wxA[3], wxB[3];
    const int nd = kh ? 2 : 3;
    const int d0 = kh ? 3 : 0;
#pragma unroll
    for (int d = 0; d < 3; d++) {
        int dd = d0 + d;
        wxA[d] = (d < nd) ? g_wx1[dd * 512 + p]       : 0.f;
        wxB[d] = (d < nd) ? g_wx1[dd * 512 + p + 256] : 0.f;
    }

    const bool ktanh = kh && (p < 128);
    const float zmul = ktanh ? 2.f : 1.f;
    const float amul = ktanh ? 2.f : 1.f;
    const float aadd = ktanh ? -1.f : 0.f;
    const int  acol  = kh ? (p + 272) : p;

    const int m  = tid & 127;
    const int cm = m + ((m >> 6) << 2);
    const int sb = tid >> 7;
    float csr[3] = {0,0,0}, sum[3] = {0,0,0}, sq[3] = {0,0,0};

    const float* xptr = xa; int xoff = 0, xsl = 0, xd = 0;
    const bool is_loader = (tid < NB * 5);
    if (is_loader) {
        xsl = tid / 5; xd = tid - 5 * xsl;
        int s = sbase + xsl, in = s >> 9, b = s & 511;
        xptr = (in == 0) ? xa : ((in == 1) ? xp : xn);
        xoff = b * (T * 5) + xd;
    }
    for (int i = tid; i < NB * HPW; i += NTH) hp[i] = 0.f;
    if (is_loader) xps[xsl][xd] = __ldg(&xptr[xoff]);
    __syncthreads();

    const uint4* Wb = g_W1h16 + (kh ? (16 << 8) : 0);
    const int hbase0 = kh ? HOFF : 0;

    for (int t = 0; t < T; t++) {
        float xnv = 0.f;
        if (is_loader && t + 1 < T) xnv = __ldg(&xptr[xoff + (t + 1) * 5]);

        ull accA[NB], accB[NB];
#pragma unroll
        for (int s = 0; s < NB; s++) {
            float dA = biasA, dB = biasB;
#pragma unroll
            for (int d = 0; d < 3; d++) {
                float xv = (d < nd) ? xps[s][d0 + d] : 0.f;
                dA = fmaf(wxA[d], xv, dA);
                dB = fmaf(wxB[d], xv, dB);
            }
            accA[s] = pk2(dA, 0.f);
            accB[s] = pk2(dB, 0.f);
        }

        uint4 wc = __ldg(Wb + p);
#pragma unroll 4
        for (int kk = 0; kk < 16; kk++) {
            int nx = ((kk + 1) & 15) << 8;
            uint4 wn = __ldg(Wb + nx + p);
            ull wAlo = h2f2(wc.x), wAhi = h2f2(wc.y);
            ull wBlo = h2f2(wc.z), wBhi = h2f2(wc.w);
            const float* hrow = hp + hbase0 + 4 * kk;
#pragma unroll
            for (int s = 0; s < NB; s++) {
                ulonglong2 hv = *(const ulonglong2*)&hrow[s * HPW];
                accA[s] = ffma2(wAlo, hv.x, accA[s]);
                accA[s] = ffma2(wAhi, hv.y, accA[s]);
                accB[s] = ffma2(wBlo, hv.x, accB[s]);
                accB[s] = ffma2(wBhi, hv.y, accB[s]);
            }
            wc = wn;
        }

#pragma unroll
        for (int s = 0; s < NB; s++) {
            float2 vA = upk2(accA[s]); float zA = vA.x + vA.y;
            float2 vB = upk2(accB[s]); float zB = vB.x + vB.y;
            zA += __shfl_xor_sync(0xffffffffu, zA, 1);
            zB += __shfl_xor_sync(0xffffffffu, zB, 1);
            float z = kh ? zB : zA;
            float sg = sigm(z * zmul);
            act[s * ACTW + acol] = fmaf(sg, amul, aadd);
        }
        __syncthreads();

        if (is_loader && t + 1 < T) xps[xsl][xd] = xnv;
#pragma unroll
        for (int r = 0; r < 3; r++) {
            int s = sb + 4 * r;
            const float* arow = act + s * ACTW;
            float gi = arow[m], gf = arow[m + 128], gg = arow[m + 272], go = arow[m + 400];
            float c = fmaf(gf, csr[r], gi * gg);
            csr[r] = c;
            float th = fmaf(2.f, sigm(2.f * c), -1.f);
            float h = go * th;
            hp[s * HPW + cm] = h;
            g_out1[((size_t)(sbase + s) * T + t) * H + m] = h;
            sum[r] += h;
            sq[r] = fmaf(h, h, sq[r]);
        }
        __syncthreads();
    }
#pragma unroll
    for (int r = 0; r < 3; r++) {
        int idx = (sbase + sb + 4 * r) * H + m;
        g_ps1[idx] = sum[r];
        g_pq1[idx] = sq[r];
    }
}

// ---------- BN stats reduce (fp64 tree, deterministic) ----------
__global__ void __launch_bounds__(128)
bn_reduce_kernel(const float* __restrict__ ps, const float* __restrict__ pq,
                 const float* __restrict__ gamma, const float* __restrict__ beta,
                 float2* __restrict__ bnout) {
    __shared__ double rs[128], rq[128];
    int cidx = blockIdx.x;
    int in = cidx >> 7, c = cidx & 127;
    int t = threadIdx.x;
    double s = 0.0, q = 0.0;
    for (int b = t; b < B; b += 128) {
        int idx = (in * B + b) * H + c;
        s += (double)ps[idx];
        q += (double)pq[idx];
    }
    rs[t] = s; rq[t] = q;
    __syncthreads();
    for (int off = 64; off > 0; off >>= 1) {
        if (t < off) { rs[t] += rs[t + off]; rq[t] += rq[t + off]; }
        __syncthreads();
    }
    if (t == 0) {
        double n = (double)B * T;
        double mean = rs[0] / n;
        double var = rq[0] / n - mean * mean;
        float scale = gamma[c] * (float)rsqrt(var + 1e-5);
        float shift = beta[c] - (float)mean * scale;
        bnout[cidx] = make_float2(scale, shift);
    }
}

// ---------- xpre GEMM: 16 tokens x 512 gates per block (proven shape), fp16 weights ----------
__global__ void __launch_bounds__(256)
xpre_kernel() {
    __shared__ __align__(16) float xs[16][H];   // 8 KB
    const int tid = threadIdx.x;
    const int tok0 = blockIdx.x * 16;

#pragma unroll
    for (int it = 0; it < 2; it++) {
        int i = tid + it * 256;          // 0..511 float4s
        int tl = i >> 5, f4 = i & 31;
        int tok = tok0 + tl;
        float4 v = __ldg(((const float4*)g_out1) + (size_t)tok * 32 + f4);
        int in = (tok >> 7) >> 9;
        int m0 = f4 * 4;
        float2 b0 = g_bn1[in * H + m0 + 0];
        float2 b1 = g_bn1[in * H + m0 + 1];
        float2 b2 = g_bn1[in * H + m0 + 2];
        float2 b3 = g_bn1[in * H + m0 + 3];
        xs[tl][m0 + 0] = fmaf(v.x, b0.x, b0.y);
        xs[tl][m0 + 1] = fmaf(v.y, b1.x, b1.y);
        xs[tl][m0 + 2] = fmaf(v.z, b2.x, b2.y);
        xs[tl][m0 + 3] = fmaf(v.w, b3.x, b3.y);
    }
    __syncthreads();

    const int p = tid;                   // gates p and p+256
    ull accA[16], accB[16];
#pragma unroll
    for (int tk = 0; tk < 16; tk++) { accA[tk] = 0ull; accB[tk] = 0ull; }

    uint4 wc = __ldg(&g_W2i16[p]);
#pragma unroll 4
    for (int k4 = 0; k4 < 32; k4++) {
        uint4 wn;
        if (k4 + 1 < 32) wn = __ldg(&g_W2i16[((k4 + 1) << 8) + p]);
        ull wAlo = h2f2(wc.x), wAhi = h2f2(wc.y);
        ull wBlo = h2f2(wc.z), wBhi = h2f2(wc.w);
#pragma unroll
        for (int tk = 0; tk < 16; tk++) {
            ulonglong2 xv = *(const ulonglong2*)&xs[tk][4 * k4];
            accA[tk] = ffma2(wAlo, xv.x, accA[tk]);
            accA[tk] = ffma2(wAhi, xv.y, accA[tk]);
            accB[tk] = ffma2(wBlo, xv.x, accB[tk]);
            accB[tk] = ffma2(wBhi, xv.y, accB[tk]);
        }
        if (k4 + 1 < 32) wc = wn;
    }
#pragma unroll
    for (int tk = 0; tk < 16; tk++) {
        float2 vA = upk2(accA[tk]);
        float2 vB = upk2(accB[tk]);
        size_t base = (size_t)(tok0 + tk) * 512;
        g_xpre[base + p]       = vA.x + vA.y;
        g_xpre[base + p + 256] = vB.x + vB.y;
    }
}

// ---------- layer 2 LSTM: recurrent part (Whh2 fp16), seed = bias + xpre ----------
__global__ void __launch_bounds__(NTH, 1)
lstm2_kernel() {
    __shared__ __align__(16) float hp[NB * HPW];
    __shared__ float act[NB * ACTW];

    const int tid = threadIdx.x;
    const int p   = tid >> 1;
    const int kh  = tid & 1;
    const int sbase = blockIdx.x * NB;

    const int myGate = p + (kh ? 256 : 0);
    const float bias = g_b2[myGate];

    const bool ktanh = kh && (p < 128);
    const float zmul = ktanh ? 2.f : 1.f;
    const float amul = ktanh ? 2.f : 1.f;
    const float aadd = ktanh ? -1.f : 0.f;
    const int  acol  = kh ? (p + 272) : p;

    const int m  = tid & 127;
    const int cm = m + ((m >> 6) << 2);
    const int sb = tid >> 7;
    float csr[3] = {0,0,0}, sum[3] = {0,0,0}, sq[3] = {0,0,0};

    for (int i = tid; i < NB * HPW; i += NTH) hp[i] = 0.f;
    __syncthreads();

    const uint4* Wb = g_W2h16 + (kh ? (16 << 8) : 0);
    const int hbase0 = kh ? HOFF : 0;

    for (int t = 0; t < T; t++) {
        float xv[NB];
#pragma unroll
        for (int s = 0; s < NB; s++)
            xv[s] = __ldg(&g_xpre[((size_t)(sbase + s) * T + t) * 512 + myGate]);

        ull accA[NB], accB[NB];
#pragma unroll
        for (int s = 0; s < NB; s++) { accA[s] = 0ull; accB[s] = 0ull; }

        uint4 wc = __ldg(Wb + p);
#pragma unroll 4
        for (int kk = 0; kk < 16; kk++) {
            int nx = ((kk + 1) & 15) << 8;
            uint4 wn = __ldg(Wb + nx + p);
            ull wAlo = h2f2(wc.x), wAhi = h2f2(wc.y);
            ull wBlo = h2f2(wc.z), wBhi = h2f2(wc.w);
            const float* hrow = hp + hbase0 + 4 * kk;
#pragma unroll
            for (int s = 0; s < NB; s++) {
                ulonglong2 hv = *(const ulonglong2*)&hrow[s * HPW];
                accA[s] = ffma2(wAlo, hv.x, accA[s]);
                accA[s] = ffma2(wAhi, hv.y, accA[s]);
                accB[s] = ffma2(wBlo, hv.x, accB[s]);
                accB[s] = ffma2(wBhi, hv.y, accB[s]);
            }
            wc = wn;
        }

#pragma unroll
        for (int s = 0; s < NB; s++) {
            float2 vA = upk2(accA[s]); float zA = vA.x + vA.y;
            float2 vB = upk2(accB[s]); float zB = vB.x + vB.y;
            float seed = bias + xv[s];
            if (kh) zB += seed; else zA += seed;
            zA += __shfl_xor_sync(0xffffffffu, zA, 1);
            zB += __shfl_xor_sync(0xffffffffu, zB, 1);
            float z = kh ? zB : zA;
            float sg = sigm(z * zmul);
            act[s * ACTW + acol] = fmaf(sg, amul, aadd);
        }
        __syncthreads();

#pragma unroll
        for (int r = 0; r < 3; r++) {
            int s = sb + 4 * r;
            const float* arow = act + s * ACTW;
            float gi = arow[m], gf = arow[m + 128], gg = arow[m + 272], go = arow[m + 400];
            float c = fmaf(gf, csr[r], gi * gg);
            csr[r] = c;
            float th = fmaf(2.f, sigm(2.f * c), -1.f);
            float h = go * th;
            hp[s * HPW + cm] = h;
            sum[r] += h;
            sq[r] = fmaf(h, h, sq[r]);
            if (t == T - 1) g_lasth[(sbase + s) * H + m] = h;
        }
        __syncthreads();
    }
#pragma unroll
    for (int r = 0; r < 3; r++) {
        int idx = (sbase + sb + 4 * r) * H + m;
        g_ps2[idx] = sum[r];
        g_pq2[idx] = sq[r];
    }
}

// ---------- FC + L2 normalize ----------
__global__ void __launch_bounds__(128)
final_kernel(const float* __restrict__ fcW, const float* __restrict__ fcb, float* __restrict__ out) {
    __shared__ float xn[H];
    __shared__ float emb[H];
    __shared__ float red[128];
    int s = blockIdx.x, j = threadIdx.x;
    int in = s >> 9, b = s & 511;

    float2 bn = g_bn2[in * H + j];
    xn[j] = fmaf(g_lasth[s * H + j], bn.x, bn.y);
    __syncthreads();

    float e = fcb[j];
    const float* wrow = fcW + j * H;
#pragma unroll 4
    for (int k = 0; k < H; k++) e = fmaf(__ldg(&wrow[k]), xn[k], e);
    emb[j] = e;
    red[j] = e * e;
    __syncthreads();
    for (int off = 64; off > 0; off >>= 1) {
        if (j < off) red[j] += red[j + off];
        __syncthreads();
    }
    float norm = sqrtf(red[0]);
    float inv = 1.f / fmaxf(norm, 1e-12f);
    out[((size_t)in * B + b) * H + j] = emb[j] * inv;
}

extern "C" void kernel_launch(void* const* d_in, const int* in_sizes, int n_in,
                              void* d_out, int out_size) {
    const float* a    = (const float*)d_in[0];
    const float* p    = (const float*)d_in[1];
    const float* n    = (const float*)d_in[2];
    const float* Wih1 = (const float*)d_in[3];
    const float* Whh1 = (const float*)d_in[4];
    const float* bih1 = (const float*)d_in[5];
    const float* bhh1 = (const float*)d_in[6];
    const float* g1   = (const float*)d_in[7];
    const float* b1   = (const float*)d_in[8];
    const float* Wih2 = (const float*)d_in[9];
    const float* Whh2 = (const float*)d_in[10];
    const float* bih2 = (const float*)d_in[11];
    const float* bhh2 = (const float*)d_in[12];
    const float* g2   = (const float*)d_in[13];
    const float* b2   = (const float*)d_in[14];
    const float* fcW  = (const float*)d_in[15];
    const float* fcb  = (const float*)d_in[16];
    float* out = (float*)d_out;

    float2 *bn1p, *bn2p;
    cudaGetSymbolAddress((void**)&bn1p, g_bn1);
    cudaGetSymbolAddress((void**)&bn2p, g_bn2);
    float *ps1, *pq1, *ps2, *pq2;
    cudaGetSymbolAddress((void**)&ps1, g_ps1);
    cudaGetSymbolAddress((void**)&pq1, g_pq1);
    cudaGetSymbolAddress((void**)&ps2, g_ps2);
    cudaGetSymbolAddress((void**)&pq2, g_pq2);

    prep_kernel<<<64, 256>>>(Wih1, Whh1, bih1, bhh1, Wih2, Whh2, bih2, bhh2);
    lstm1_kernel<<<NBLK, NTH>>>(a, p, n);
    bn_reduce_kernel<<<3 * H, 128>>>(ps1, pq1, g1, b1, bn1p);
    xpre_kernel<<<(S * T) / 16, 256>>>();
    lstm2_kernel<<<NBLK, NTH>>>();
    bn_reduce_kernel<<<3 * H, 128>>>(ps2, pq2, g2, b2, bn2p);
    final_kernel<<<S, 128>>>(fcW, fcb, out);
}

// round 12
// speedup vs baseline: 1.6942x; 1.5448x over previous
#include <cuda_runtime.h>
#include <math.h>
#include <stdint.h>

constexpr int H    = 128;
constexpr int B    = 512;
constexpr int T    = 128;
constexpr int S    = 1536;   // 3 inputs * B
constexpr int NB   = 12;     // seqs per block
constexpr int NBLK = 128;
constexpr int NTH  = 512;

constexpr int HPW  = 132;    // padded h row
constexpr int HOFF = 68;
constexpr int ACTW = 528;

// dynamic smem layout (float units)
constexpr int RING_F4   = 4 * 1024;            // 4 slots x 1024 float4 = 64 KB
constexpr int SM_HP     = RING_F4 * 4;         // float offset
constexpr int SM_ACT    = SM_HP + NB * HPW;
constexpr int SM_XPS    = SM_ACT + NB * ACTW;
constexpr int SMEM_FLOATS = SM_XPS + 64;
constexpr int SMEM_BYTES  = SMEM_FLOATS * 4;   // ~95 KB

// k4-major packed weights: g_W[k4*512 + j] = {W[j][4k4..4k4+3]}
__device__ float4 g_W1h[32 * 512];
__device__ float4 g_W2i[32 * 512];
__device__ float4 g_W2h[32 * 512];
__device__ float  g_b1[512];
__device__ float  g_b2[512];
__device__ float  g_wx1[5 * 512];
__device__ float  g_out1[(size_t)S * T * H];
__device__ float  g_xpre[(size_t)S * T * 512];
__device__ float  g_lasth[S * H];
__device__ float  g_ps1[S * H];
__device__ float  g_pq1[S * H];
__device__ float  g_ps2[S * H];
__device__ float  g_pq2[S * H];
__device__ float2 g_bn1[3 * H];
__device__ float2 g_bn2[3 * H];

typedef unsigned long long ull;

__device__ __forceinline__ ull pk2(float x, float y) {
    ull r;
    asm("mov.b64 %0, {%1,%2};" : "=l"(r) : "r"(__float_as_uint(x)), "r"(__float_as_uint(y)));
    return r;
}
__device__ __forceinline__ float2 upk2(ull v) {
    unsigned lo, hi;
    asm("mov.b64 {%0,%1}, %2;" : "=r"(lo), "=r"(hi) : "l"(v));
    return make_float2(__uint_as_float(lo), __uint_as_float(hi));
}
__device__ __forceinline__ ull ffma2(ull a, ull b, ull c) {
    ull d;
    asm("fma.rn.f32x2 %0, %1, %2, %3;" : "=l"(d) : "l"(a), "l"(b), "l"(c));
    return d;
}
__device__ __forceinline__ float sigm(float x) {
    return __fdividef(1.f, 1.f + __expf(-x));
}
__device__ __forceinline__ void cpa16(unsigned dst, const void* src) {
    asm volatile("cp.async.cg.shared.global [%0], [%1], 16;" :: "r"(dst), "l"(src));
}
__device__ __forceinline__ void cpa_commit() {
    asm volatile("cp.async.commit_group;" ::: "memory");
}
__device__ __forceinline__ void cpa_wait2() {
    asm volatile("cp.async.wait_group 2;" ::: "memory");
}
__device__ __forceinline__ void cpa_wait0() {
    asm volatile("cp.async.wait_group 0;" ::: "memory");
}

// ---------- pack weights ----------
__global__ void prep_kernel(const float* Wih1, const float* Whh1, const float* bih1, const float* bhh1,
                            const float* Wih2, const float* Whh2, const float* bih2, const float* bhh2) {
    int tid = blockIdx.x * blockDim.x + threadIdx.x;
    int stride = gridDim.x * blockDim.x;
    for (int idx = tid; idx < 32 * 512; idx += stride) {
        int k4 = idx >> 9, j = idx & 511;
        g_W1h[idx] = *(const float4*)&Whh1[j * H + 4 * k4];
        g_W2i[idx] = *(const float4*)&Wih2[j * H + 4 * k4];
        g_W2h[idx] = *(const float4*)&Whh2[j * H + 4 * k4];
    }
    for (int j = tid; j < 512; j += stride) {
        g_b1[j] = bih1[j] + bhh1[j];
        g_b2[j] = bih2[j] + bhh2[j];
        for (int d = 0; d < 5; d++) g_wx1[d * 512 + j] = Wih1[j * 5 + d];
    }
}

// ---------- layer 1 LSTM ----------
// thread = gate-pair p = tid>>1 (gates p, p+256) x k-half kh = tid&1 (lane parity)
__global__ void __launch_bounds__(NTH, 1)
lstm1_kernel(const float* __restrict__ xa, const float* __restrict__ xp, const float* __restrict__ xn) {
    extern __shared__ __align__(16) float smem[];
    float4* ringf4 = (float4*)smem;
    float*  hp  = smem + SM_HP;
    float*  act = smem + SM_ACT;
    float*  xps = smem + SM_XPS;

    const int tid = threadIdx.x;
    const int p   = tid >> 1;
    const int kh  = tid & 1;
    const int sbase = blockIdx.x * NB;

    const float biasA = kh ? 0.f : g_b1[p];
    const float biasB = kh ? 0.f : g_b1[p + 256];
    float wxA[3], wxB[3];
    const int nd = kh ? 2 : 3;
    const int d0 = kh ? 3 : 0;
#pragma unroll
    for (int d = 0; d < 3; d++) {
        int dd = d0 + d;
        wxA[d] = (d < nd) ? g_wx1[dd * 512 + p]       : 0.f;
        wxB[d] = (d < nd) ? g_wx1[dd * 512 + p + 256] : 0.f;
    }

    const bool ktanh = kh && (p < 128);
    const float zmul = ktanh ? 2.f : 1.f;
    const float amul = ktanh ? 2.f : 1.f;
    const float aadd = ktanh ? -1.f : 0.f;
    const int  acol  = kh ? (p + 272) : p;

    const int m  = tid & 127;
    const int cm = m + ((m >> 6) << 2);
    const int sb = tid >> 7;
    float csr[3] = {0,0,0}, sum[3] = {0,0,0}, sq[3] = {0,0,0};

    const float* xptr = xa; int xoff = 0, xsl = 0, xd = 0;
    const bool is_loader = (tid < NB * 5);
    if (is_loader) {
        xsl = tid / 5; xd = tid - 5 * xsl;
        int s = sbase + xsl, in = s >> 9, b = s & 511;
        xptr = (in == 0) ? xa : ((in == 1) ? xp : xn);
        xoff = b * (T * 5) + xd;
    }
    for (int i = tid; i < NB * HPW; i += NTH) hp[i] = 0.f;
    if (is_loader) xps[xsl * 5 + xd] = __ldg(&xptr[xoff]);
    __syncthreads();

    const float4* Wb = g_W1h + (kh ? (16 << 9) : 0);
    const int woff   = kh ? 512 : 0;
    const int hbase0 = kh ? HOFF : 0;
    const unsigned ring_u32 = (unsigned)__cvta_generic_to_shared(ringf4);
    const unsigned dbase = ring_u32 + (woff + p) * 16;

    // pipeline prologue: chunks 0,1,2
#pragma unroll
    for (int c = 0; c < 3; c++) {
        const float4* src = Wb + (c << 9) + p;
        unsigned dst = dbase + ((c & 3) << 14);
        cpa16(dst, src);
        cpa16(dst + 4096, src + 256);
        cpa_commit();
    }

    for (int t = 0; t < T; t++) {
        float xnv = 0.f;
        if (is_loader && t + 1 < T) xnv = __ldg(&xptr[xoff + (t + 1) * 5]);

        ull accA[NB], accB[NB];
#pragma unroll
        for (int s = 0; s < NB; s++) {
            float dA = biasA, dB = biasB;
#pragma unroll
            for (int d = 0; d < 3; d++) {
                float xv = (d < nd) ? xps[s * 5 + d0 + d] : 0.f;
                dA = fmaf(wxA[d], xv, dA);
                dB = fmaf(wxB[d], xv, dB);
            }
            accA[s] = pk2(dA, 0.f);
            accB[s] = pk2(dB, 0.f);
        }

#pragma unroll 4
        for (int kk = 0; kk < 16; kk++) {
            cpa_wait2();                              // stage kk ready
            const float4* wsl = ringf4 + ((kk & 3) << 10) + woff + p;
            float4 wA = wsl[0];
            float4 wB = wsl[256];
            // issue chunk (kk+3)&15 -> continuous pipeline across steps
            {
                int c = (kk + 3) & 15;
                const float4* src = Wb + (c << 9) + p;
                unsigned dst = dbase + ((c & 3) << 14);
                cpa16(dst, src);
                cpa16(dst + 4096, src + 256);
                cpa_commit();
            }
            ull wAlo = pk2(wA.x, wA.y), wAhi = pk2(wA.z, wA.w);
            ull wBlo = pk2(wB.x, wB.y), wBhi = pk2(wB.z, wB.w);
            const float* hrow = hp + hbase0 + 4 * kk;
#pragma unroll
            for (int s = 0; s < NB; s++) {
                ulonglong2 hv = *(const ulonglong2*)&hrow[s * HPW];
                accA[s] = ffma2(wAlo, hv.x, accA[s]);
                accA[s] = ffma2(wAhi, hv.y, accA[s]);
                accB[s] = ffma2(wBlo, hv.x, accB[s]);
                accB[s] = ffma2(wBhi, hv.y, accB[s]);
            }
        }

#pragma unroll
        for (int s = 0; s < NB; s++) {
            float2 vA = upk2(accA[s]); float zA = vA.x + vA.y;
            float2 vB = upk2(accB[s]); float zB = vB.x + vB.y;
            zA += __shfl_xor_sync(0xffffffffu, zA, 1);
            zB += __shfl_xor_sync(0xffffffffu, zB, 1);
            float z = kh ? zB : zA;
            float sg = sigm(z * zmul);
            act[s * ACTW + acol] = fmaf(sg, amul, aadd);
        }
        __syncthreads();

        if (is_loader && t + 1 < T) xps[xsl * 5 + xd] = xnv;
#pragma unroll
        for (int r = 0; r < 3; r++) {
            int s = sb + 4 * r;
            const float* arow = act + s * ACTW;
            float gi = arow[m], gf = arow[m + 128], gg = arow[m + 272], go = arow[m + 400];
            float c = fmaf(gf, csr[r], gi * gg);
            csr[r] = c;
            float th = fmaf(2.f, sigm(2.f * c), -1.f);
            float h = go * th;
            hp[s * HPW + cm] = h;
            g_out1[((size_t)(sbase + s) * T + t) * H + m] = h;
            sum[r] += h;
            sq[r] = fmaf(h, h, sq[r]);
        }
        __syncthreads();
    }
    cpa_wait0();
#pragma unroll
    for (int r = 0; r < 3; r++) {
        int idx = (sbase + sb + 4 * r) * H + m;
        g_ps1[idx] = sum[r];
        g_pq1[idx] = sq[r];
    }
}

// ---------- BN stats reduce (fp64 tree, deterministic) ----------
__global__ void __launch_bounds__(128)
bn_reduce_kernel(const float* __restrict__ ps, const float* __restrict__ pq,
                 const float* __restrict__ gamma, const float* __restrict__ beta,
                 float2* __restrict__ bnout) {
    __shared__ double rs[128], rq[128];
    int cidx = blockIdx.x;
    int in = cidx >> 7, c = cidx & 127;
    int t = threadIdx.x;
    double s = 0.0, q = 0.0;
    for (int b = t; b < B; b += 128) {
        int idx = (in * B + b) * H + c;
        s += (double)ps[idx];
        q += (double)pq[idx];
    }
    rs[t] = s; rq[t] = q;
    __syncthreads();
    for (int off = 64; off > 0; off >>= 1) {
        if (t < off) { rs[t] += rs[t + off]; rq[t] += rq[t + off]; }
        __syncthreads();
    }
    if (t == 0) {
        double n = (double)B * T;
        double mean = rs[0] / n;
        double var = rq[0] / n - mean * mean;
        float scale = gamma[c] * (float)rsqrt(var + 1e-5);
        float shift = beta[c] - (float)mean * scale;
        bnout[cidx] = make_float2(scale, shift);
    }
}

// ---------- xpre GEMM: 16 tokens x 512 gates per block (R9 proven shape) ----------
__global__ void __launch_bounds__(256)
xpre_kernel() {
    __shared__ __align__(16) float xs[16][H];   // 8 KB
    const int tid = threadIdx.x;
    const int tok0 = blockIdx.x * 16;

#pragma unroll
    for (int it = 0; it < 2; it++) {
        int i = tid + it * 256;
        int tl = i >> 5, f4 = i & 31;
        int tok = tok0 + tl;
        float4 v = __ldg(((const float4*)g_out1) + (size_t)tok * 32 + f4);
        int in = (tok >> 7) >> 9;
        int m0 = f4 * 4;
        float2 b0 = g_bn1[in * H + m0 + 0];
        float2 b1 = g_bn1[in * H + m0 + 1];
        float2 b2 = g_bn1[in * H + m0 + 2];
        float2 b3 = g_bn1[in * H + m0 + 3];
        xs[tl][m0 + 0] = fmaf(v.x, b0.x, b0.y);
        xs[tl][m0 + 1] = fmaf(v.y, b1.x, b1.y);
        xs[tl][m0 + 2] = fmaf(v.z, b2.x, b2.y);
        xs[tl][m0 + 3] = fmaf(v.w, b3.x, b3.y);
    }
    __syncthreads();

    const int p = tid;                   // gates p and p+256
    ull accA[16], accB[16];
#pragma unroll
    for (int tk = 0; tk < 16; tk++) { accA[tk] = 0ull; accB[tk] = 0ull; }

#pragma unroll 4
    for (int k4 = 0; k4 < 32; k4++) {
        float4 wA = __ldg(&g_W2i[(k4 << 9) + p]);
        float4 wB = __ldg(&g_W2i[(k4 << 9) + p + 256]);
        ull wAlo = pk2(wA.x, wA.y), wAhi = pk2(wA.z, wA.w);
        ull wBlo = pk2(wB.x, wB.y), wBhi = pk2(wB.z, wB.w);
#pragma unroll
        for (int tk = 0; tk < 16; tk++) {
            ulonglong2 xv = *(const ulonglong2*)&xs[tk][4 * k4];
            accA[tk] = ffma2(wAlo, xv.x, accA[tk]);
            accA[tk] = ffma2(wAhi, xv.y, accA[tk]);
            accB[tk] = ffma2(wBlo, xv.x, accB[tk]);
            accB[tk] = ffma2(wBhi, xv.y, accB[tk]);
        }
    }
#pragma unroll
    for (int tk = 0; tk < 16; tk++) {
        float2 vA = upk2(accA[tk]);
        float2 vB = upk2(accB[tk]);
        size_t base = (size_t)(tok0 + tk) * 512;
        g_xpre[base + p]       = vA.x + vA.y;
        g_xpre[base + p + 256] = vB.x + vB.y;
    }
}

// ---------- layer 2 LSTM: recurrent part (Whh2), seed = bias + xpre ----------
__global__ void __launch_bounds__(NTH, 1)
lstm2_kernel() {
    extern __shared__ __align__(16) float smem[];
    float4* ringf4 = (float4*)smem;
    float*  hp  = smem + SM_HP;
    float*  act = smem + SM_ACT;

    const int tid = threadIdx.x;
    const int p   = tid >> 1;
    const int kh  = tid & 1;
    const int sbase = blockIdx.x * NB;

    const int myGate = p + (kh ? 256 : 0);
    const float bias = g_b2[myGate];

    const bool ktanh = kh && (p < 128);
    const float zmul = ktanh ? 2.f : 1.f;
    const float amul = ktanh ? 2.f : 1.f;
    const float aadd = ktanh ? -1.f : 0.f;
    const int  acol  = kh ? (p + 272) : p;

    const int m  = tid & 127;
    const int cm = m + ((m >> 6) << 2);
    const int sb = tid >> 7;
    float csr[3] = {0,0,0}, sum[3] = {0,0,0}, sq[3] = {0,0,0};

    for (int i = tid; i < NB * HPW; i += NTH) hp[i] = 0.f;
    __syncthreads();

    const float4* Wb = g_W2h + (kh ? (16 << 9) : 0);
    const int woff   = kh ? 512 : 0;
    const int hbase0 = kh ? HOFF : 0;
    const unsigned ring_u32 = (unsigned)__cvta_generic_to_shared(ringf4);
    const unsigned dbase = ring_u32 + (woff + p) * 16;

#pragma unroll
    for (int c = 0; c < 3; c++) {
        const float4* src = Wb + (c << 9) + p;
        unsigned dst = dbase + ((c & 3) << 14);
        cpa16(dst, src);
        cpa16(dst + 4096, src + 256);
        cpa_commit();
    }

    for (int t = 0; t < T; t++) {
        float xv[NB];
#pragma unroll
        for (int s = 0; s < NB; s++)
            xv[s] = __ldg(&g_xpre[((size_t)(sbase + s) * T + t) * 512 + myGate]);

        ull accA[NB], accB[NB];
#pragma unroll
        for (int s = 0; s < NB; s++) { accA[s] = 0ull; accB[s] = 0ull; }

#pragma unroll 4
        for (int kk = 0; kk < 16; kk++) {
            cpa_wait2();
            const float4* wsl = ringf4 + ((kk & 3) << 10) + woff + p;
            float4 wA = wsl[0];
            float4 wB = wsl[256];
            {
                int c = (kk + 3) & 15;
                const float4* src = Wb + (c << 9) + p;
                unsigned dst = dbase + ((c & 3) << 14);
                cpa16(dst, src);
                cpa16(dst + 4096, src + 256);
                cpa_commit();
            }
            ull wAlo = pk2(wA.x, wA.y), wAhi = pk2(wA.z, wA.w);
            ull wBlo = pk2(wB.x, wB.y), wBhi = pk2(wB.z, wB.w);
            const float* hrow = hp + hbase0 + 4 * kk;
#pragma unroll
            for (int s = 0; s < NB; s++) {
                ulonglong2 hv = *(const ulonglong2*)&hrow[s * HPW];
                accA[s] = ffma2(wAlo, hv.x, accA[s]);
                accA[s] = ffma2(wAhi, hv.y, accA[s]);
                accB[s] = ffma2(wBlo, hv.x, accB[s]);
                accB[s] = ffma2(wBhi, hv.y, accB[s]);
            }
        }

#pragma unroll
        for (int s = 0; s < NB; s++) {
            float2 vA = upk2(accA[s]); float zA = vA.x + vA.y;
            float2 vB = upk2(accB[s]); float zB = vB.x + vB.y;
            float seed = bias + xv[s];
            if (kh) zB += seed; else zA += seed;
            zA += __shfl_xor_sync(0xffffffffu, zA, 1);
            zB += __shfl_xor_sync(0xffffffffu, zB, 1);
            float z = kh ? zB : zA;
            float sg = sigm(z * zmul);
            act[s * ACTW + acol] = fmaf(sg, amul, aadd);
        }
        __syncthreads();

#pragma unroll
        for (int r = 0; r < 3; r++) {
            int s = sb + 4 * r;
            const float* arow = act + s * ACTW;
            float gi = arow[m], gf = arow[m + 128], gg = arow[m + 272], go = arow[m + 400];
            float c = fmaf(gf, csr[r], gi * gg);
            csr[r] = c;
            float th = fmaf(2.f, sigm(2.f * c), -1.f);
            float h = go * th;
            hp[s * HPW + cm] = h;
            sum[r] += h;
            sq[r] = fmaf(h, h, sq[r]);
            if (t == T - 1) g_lasth[(sbase + s) * H + m] = h;
        }
        __syncthreads();
    }
    cpa_wait0();
#pragma unroll
    for (int r = 0; r < 3; r++) {
        int idx = (sbase + sb + 4 * r) * H + m;
        g_ps2[idx] = sum[r];
        g_pq2[idx] = sq[r];
    }
}

// ---------- FC + L2 normalize ----------
__global__ void __launch_bounds__(128)
final_kernel(const float* __restrict__ fcW, const float* __restrict__ fcb, float* __restrict__ out) {
    __shared__ float xn[H];
    __shared__ float emb[H];
    __shared__ float red[128];
    int s = blockIdx.x, j = threadIdx.x;
    int in = s >> 9, b = s & 511;

    float2 bn = g_bn2[in * H + j];
    xn[j] = fmaf(g_lasth[s * H + j], bn.x, bn.y);
    __syncthreads();

    float e = fcb[j];
    const float* wrow = fcW + j * H;
#pragma unroll 4
    for (int k = 0; k < H; k++) e = fmaf(__ldg(&wrow[k]), xn[k], e);
    emb[j] = e;
    red[j] = e * e;
    __syncthreads();
    for (int off = 64; off > 0; off >>= 1) {
        if (j < off) red[j] += red[j + off];
        __syncthreads();
    }
    float norm = sqrtf(red[0]);
    float inv = 1.f / fmaxf(norm, 1e-12f);
    out[((size_t)in * B + b) * H + j] = emb[j] * inv;
}

extern "C" void kernel_launch(void* const* d_in, const int* in_sizes, int n_in,
                              void* d_out, int out_size) {
    const float* a    = (const float*)d_in[0];
    const float* p    = (const float*)d_in[1];
    const float* n    = (const float*)d_in[2];
    const float* Wih1 = (const float*)d_in[3];
    const float* Whh1 = (const float*)d_in[4];
    const float* bih1 = (const float*)d_in[5];
    const float* bhh1 = (const float*)d_in[6];
    const float* g1   = (const float*)d_in[7];
    const float* b1   = (const float*)d_in[8];
    const float* Wih2 = (const float*)d_in[9];
    const float* Whh2 = (const float*)d_in[10];
    const float* bih2 = (const float*)d_in[11];
    const float* bhh2 = (const float*)d_in[12];
    const float* g2   = (const float*)d_in[13];
    const float* b2   = (const float*)d_in[14];
    const float* fcW  = (const float*)d_in[15];
    const float* fcb  = (const float*)d_in[16];
    float* out = (float*)d_out;

    cudaFuncSetAttribute(lstm1_kernel, cudaFuncAttributeMaxDynamicSharedMemorySize, SMEM_BYTES);
    cudaFuncSetAttribute(lstm2_kernel, cudaFuncAttributeMaxDynamicSharedMemorySize, SMEM_BYTES);

    float2 *bn1p, *bn2p;
    cudaGetSymbolAddress((void**)&bn1p, g_bn1);
    cudaGetSymbolAddress((void**)&bn2p, g_bn2);
    float *ps1, *pq1, *ps2, *pq2;
    cudaGetSymbolAddress((void**)&ps1, g_ps1);
    cudaGetSymbolAddress((void**)&pq1, g_pq1);
    cudaGetSymbolAddress((void**)&ps2, g_ps2);
    cudaGetSymbolAddress((void**)&pq2, g_pq2);

    prep_kernel<<<64, 256>>>(Wih1, Whh1, bih1, bhh1, Wih2, Whh2, bih2, bhh2);
    lstm1_kernel<<<NBLK, NTH, SMEM_BYTES>>>(a, p, n);
    bn_reduce_kernel<<<3 * H, 128>>>(ps1, pq1, g1, b1, bn1p);
    xpre_kernel<<<(S * T) / 16, 256>>>();
    lstm2_kernel<<<NBLK, NTH, SMEM_BYTES>>>();
    bn_reduce_kernel<<<3 * H, 128>>>(ps2, pq2, g2, b2, bn2p);
    final_kernel<<<S, 128>>>(fcW, fcb, out);
}

// round 13
// speedup vs baseline: 1.9832x; 1.1706x over previous
#include <cuda_runtime.h>
#include <cuda_fp16.h>
#include <math.h>
#include <stdint.h>

constexpr int H    = 128;
constexpr int B    = 512;
constexpr int T    = 128;
constexpr int S    = 1536;   // 3 inputs * B
constexpr int NB   = 12;     // seqs per block
constexpr int NBLK = 128;
constexpr int NTH  = 512;

constexpr int HPW  = 132;    // padded h row
constexpr int HOFF = 68;
constexpr int ACTW = 528;

// dynamic smem layout for lstm kernels (float units)
constexpr int RING_F4   = 4 * 1024;            // 4 slots x 1024 float4 = 64 KB
constexpr int SM_HP     = RING_F4 * 4;
constexpr int SM_ACT    = SM_HP + NB * HPW;
constexpr int SM_XPS    = SM_ACT + NB * ACTW;
constexpr int SMEM_FLOATS = SM_XPS + 64;
constexpr int SMEM_BYTES  = SMEM_FLOATS * 4;   // ~95 KB

// xpre mma smem: W (512 x 136 halves) + x (64 x 136 halves)
constexpr int XSW = 136;
constexpr int XP_W_HALFS = 512 * XSW;          // 69632
constexpr int XP_X_HALFS = 64 * XSW;           // 8704
constexpr int XP_SMEM_BYTES = (XP_W_HALFS + XP_X_HALFS) * 2;   // ~153 KB

// k4-major packed weights: g_W[k4*512 + j] = {W[j][4k4..4k4+3]}
__device__ float4 g_W1h[32 * 512];
__device__ float4 g_W2h[32 * 512];
__device__ __half g_W2ih[512 * 128];           // row-major fp16 Wih2
__device__ float  g_b1[512];
__device__ float  g_b2[512];
__device__ float  g_wx1[5 * 512];
__device__ float  g_out1[(size_t)S * T * H];
__device__ float  g_xpre[(size_t)S * T * 512];
__device__ float  g_lasth[S * H];
__device__ float  g_ps1[S * H];
__device__ float  g_pq1[S * H];
__device__ float  g_ps2[S * H];
__device__ float  g_pq2[S * H];
__device__ float2 g_bn1[3 * H];
__device__ float2 g_bn2[3 * H];

typedef unsigned long long ull;

__device__ __forceinline__ ull pk2(float x, float y) {
    ull r;
    asm("mov.b64 %0, {%1,%2};" : "=l"(r) : "r"(__float_as_uint(x)), "r"(__float_as_uint(y)));
    return r;
}
__device__ __forceinline__ float2 upk2(ull v) {
    unsigned lo, hi;
    asm("mov.b64 {%0,%1}, %2;" : "=r"(lo), "=r"(hi) : "l"(v));
    return make_float2(__uint_as_float(lo), __uint_as_float(hi));
}
__device__ __forceinline__ ull ffma2(ull a, ull b, ull c) {
    ull d;
    asm("fma.rn.f32x2 %0, %1, %2, %3;" : "=l"(d) : "l"(a), "l"(b), "l"(c));
    return d;
}
__device__ __forceinline__ float sigm(float x) {
    return __fdividef(1.f, 1.f + __expf(-x));
}
__device__ __forceinline__ void cpa16(unsigned dst, const void* src) {
    asm volatile("cp.async.cg.shared.global [%0], [%1], 16;" :: "r"(dst), "l"(src));
}
__device__ __forceinline__ void cpa_commit() {
    asm volatile("cp.async.commit_group;" ::: "memory");
}
__device__ __forceinline__ void cpa_wait2() {
    asm volatile("cp.async.wait_group 2;" ::: "memory");
}
__device__ __forceinline__ void cpa_wait0() {
    asm volatile("cp.async.wait_group 0;" ::: "memory");
}
__device__ __forceinline__ void mma16816(float& d0, float& d1, float& d2, float& d3,
                                         unsigned a0, unsigned a1, unsigned a2, unsigned a3,
                                         unsigned b0, unsigned b1) {
    asm volatile("mma.sync.aligned.m16n8k16.row.col.f32.f16.f16.f32 "
                 "{%0,%1,%2,%3}, {%4,%5,%6,%7}, {%8,%9}, {%0,%1,%2,%3};"
                 : "+f"(d0), "+f"(d1), "+f"(d2), "+f"(d3)
                 : "r"(a0), "r"(a1), "r"(a2), "r"(a3), "r"(b0), "r"(b1));
}

// ---------- pack weights ----------
__global__ void prep_kernel(const float* Wih1, const float* Whh1, const float* bih1, const float* bhh1,
                            const float* Wih2, const float* Whh2, const float* bih2, const float* bhh2) {
    int tid = blockIdx.x * blockDim.x + threadIdx.x;
    int stride = gridDim.x * blockDim.x;
    for (int idx = tid; idx < 32 * 512; idx += stride) {
        int k4 = idx >> 9, j = idx & 511;
        g_W1h[idx] = *(const float4*)&Whh1[j * H + 4 * k4];
        g_W2h[idx] = *(const float4*)&Whh2[j * H + 4 * k4];
    }
    for (int idx = tid; idx < 512 * 128; idx += stride) {
        g_W2ih[idx] = __float2half(Wih2[idx]);
    }
    for (int j = tid; j < 512; j += stride) {
        g_b1[j] = bih1[j] + bhh1[j];
        g_b2[j] = bih2[j] + bhh2[j];
        for (int d = 0; d < 5; d++) g_wx1[d * 512 + j] = Wih1[j * 5 + d];
    }
}

// ---------- layer 1 LSTM (R12 structure, cp.async ring) ----------
__global__ void __launch_bounds__(NTH, 1)
lstm1_kernel(const float* __restrict__ xa, const float* __restrict__ xp, const float* __restrict__ xn) {
    extern __shared__ __align__(16) float smem[];
    float4* ringf4 = (float4*)smem;
    float*  hp  = smem + SM_HP;
    float*  act = smem + SM_ACT;
    float*  xps = smem + SM_XPS;

    const int tid = threadIdx.x;
    const int p   = tid >> 1;
    const int kh  = tid & 1;
    const int sbase = blockIdx.x * NB;

    const float biasA = kh ? 0.f : g_b1[p];
    const float biasB = kh ? 0.f : g_b1[p + 256];
    float wxA[3], wxB[3];
    const int nd = kh ? 2 : 3;
    const int d0 = kh ? 3 : 0;
#pragma unroll
    for (int d = 0; d < 3; d++) {
        int dd = d0 + d;
        wxA[d] = (d < nd) ? g_wx1[dd * 512 + p]       : 0.f;
        wxB[d] = (d < nd) ? g_wx1[dd * 512 + p + 256] : 0.f;
    }

    const bool ktanh = kh && (p < 128);
    const float zmul = ktanh ? 2.f : 1.f;
    const float amul = ktanh ? 2.f : 1.f;
    const float aadd = ktanh ? -1.f : 0.f;
    const int  acol  = kh ? (p + 272) : p;

    const int m  = tid & 127;
    const int cm = m + ((m >> 6) << 2);
    const int sb = tid >> 7;
    float csr[3] = {0,0,0}, sum[3] = {0,0,0}, sq[3] = {0,0,0};

    const float* xptr = xa; int xoff = 0, xsl = 0, xd = 0;
    const bool is_loader = (tid < NB * 5);
    if (is_loader) {
        xsl = tid / 5; xd = tid - 5 * xsl;
        int s = sbase + xsl, in = s >> 9, b = s & 511;
        xptr = (in == 0) ? xa : ((in == 1) ? xp : xn);
        xoff = b * (T * 5) + xd;
    }
    for (int i = tid; i < NB * HPW; i += NTH) hp[i] = 0.f;
    if (is_loader) xps[xsl * 5 + xd] = __ldg(&xptr[xoff]);
    __syncthreads();

    const float4* Wb = g_W1h + (kh ? (16 << 9) : 0);
    const int woff   = kh ? 512 : 0;
    const int hbase0 = kh ? HOFF : 0;
    const unsigned ring_u32 = (unsigned)__cvta_generic_to_shared(ringf4);
    const unsigned dbase = ring_u32 + (woff + p) * 16;

#pragma unroll
    for (int c = 0; c < 3; c++) {
        const float4* src = Wb + (c << 9) + p;
        unsigned dst = dbase + ((c & 3) << 14);
        cpa16(dst, src);
        cpa16(dst + 4096, src + 256);
        cpa_commit();
    }

    for (int t = 0; t < T; t++) {
        float xnv = 0.f;
        if (is_loader && t + 1 < T) xnv = __ldg(&xptr[xoff + (t + 1) * 5]);

        ull accA[NB], accB[NB];
#pragma unroll
        for (int s = 0; s < NB; s++) {
            float dA = biasA, dB = biasB;
#pragma unroll
            for (int d = 0; d < 3; d++) {
                float xv = (d < nd) ? xps[s * 5 + d0 + d] : 0.f;
                dA = fmaf(wxA[d], xv, dA);
                dB = fmaf(wxB[d], xv, dB);
            }
            accA[s] = pk2(dA, 0.f);
            accB[s] = pk2(dB, 0.f);
        }

#pragma unroll 4
        for (int kk = 0; kk < 16; kk++) {
            cpa_wait2();
            const float4* wsl = ringf4 + ((kk & 3) << 10) + woff + p;
            float4 wA = wsl[0];
            float4 wB = wsl[256];
            {
                int c = (kk + 3) & 15;
                const float4* src = Wb + (c << 9) + p;
                unsigned dst = dbase + ((c & 3) << 14);
                cpa16(dst, src);
                cpa16(dst + 4096, src + 256);
                cpa_commit();
            }
            ull wAlo = pk2(wA.x, wA.y), wAhi = pk2(wA.z, wA.w);
            ull wBlo = pk2(wB.x, wB.y), wBhi = pk2(wB.z, wB.w);
            const float* hrow = hp + hbase0 + 4 * kk;
#pragma unroll
            for (int s = 0; s < NB; s++) {
                ulonglong2 hv = *(const ulonglong2*)&hrow[s * HPW];
                accA[s] = ffma2(wAlo, hv.x, accA[s]);
                accA[s] = ffma2(wAhi, hv.y, accA[s]);
                accB[s] = ffma2(wBlo, hv.x, accB[s]);
                accB[s] = ffma2(wBhi, hv.y, accB[s]);
            }
        }

#pragma unroll
        for (int s = 0; s < NB; s++) {
            float2 vA = upk2(accA[s]); float zA = vA.x + vA.y;
            float2 vB = upk2(accB[s]); float zB = vB.x + vB.y;
            zA += __shfl_xor_sync(0xffffffffu, zA, 1);
            zB += __shfl_xor_sync(0xffffffffu, zB, 1);
            float z = kh ? zB : zA;
            float sg = sigm(z * zmul);
            act[s * ACTW + acol] = fmaf(sg, amul, aadd);
        }
        __syncthreads();

        if (is_loader && t + 1 < T) xps[xsl * 5 + xd] = xnv;
#pragma unroll
        for (int r = 0; r < 3; r++) {
            int s = sb + 4 * r;
            const float* arow = act + s * ACTW;
            float gi = arow[m], gf = arow[m + 128], gg = arow[m + 272], go = arow[m + 400];
            float c = fmaf(gf, csr[r], gi * gg);
            csr[r] = c;
            float th = fmaf(2.f, sigm(2.f * c), -1.f);
            float h = go * th;
            hp[s * HPW + cm] = h;
            g_out1[((size_t)(sbase + s) * T + t) * H + m] = h;
            sum[r] += h;
            sq[r] = fmaf(h, h, sq[r]);
        }
        __syncthreads();
    }
    cpa_wait0();
#pragma unroll
    for (int r = 0; r < 3; r++) {
        int idx = (sbase + sb + 4 * r) * H + m;
        g_ps1[idx] = sum[r];
        g_pq1[idx] = sq[r];
    }
}

// ---------- BN stats reduce (fp64 tree, deterministic) ----------
__global__ void __launch_bounds__(128)
bn_reduce_kernel(const float* __restrict__ ps, const float* __restrict__ pq,
                 const float* __restrict__ gamma, const float* __restrict__ beta,
                 float2* __restrict__ bnout) {
    __shared__ double rs[128], rq[128];
    int cidx = blockIdx.x;
    int in = cidx >> 7, c = cidx & 127;
    int t = threadIdx.x;
    double s = 0.0, q = 0.0;
    for (int b = t; b < B; b += 128) {
        int idx = (in * B + b) * H + c;
        s += (double)ps[idx];
        q += (double)pq[idx];
    }
    rs[t] = s; rq[t] = q;
    __syncthreads();
    for (int off = 64; off > 0; off >>= 1) {
        if (t < off) { rs[t] += rs[t + off]; rq[t] += rq[t + off]; }
        __syncthreads();
    }
    if (t == 0) {
        double n = (double)B * T;
        double mean = rs[0] / n;
        double var = rq[0] / n - mean * mean;
        float scale = gamma[c] * (float)rsqrt(var + 1e-5);
        float shift = beta[c] - (float)mean * scale;
        bnout[cidx] = make_float2(scale, shift);
    }
}

// ---------- xpre GEMM via HMMA: 64 tokens x 512 gates per block ----------
// warp (16 total): mt2 = w>>3 (token half), ng = w&7 (64-gate group)
__global__ void __launch_bounds__(512)
xpre_kernel() {
    extern __shared__ __align__(16) __half hsm[];
    __half* Wsh = hsm;                    // [512][XSW]
    __half* xsh = hsm + XP_W_HALFS;       // [64][XSW]

    const int tid  = threadIdx.x;
    const int tok0 = blockIdx.x * 64;

    // stage W2i (fp16) into smem: 512 gates x 16 uint4 chunks
    for (int idx = tid; idx < 512 * 16; idx += 512) {
        int gate = idx >> 4, c = idx & 15;
        uint4 v = *(const uint4*)(g_W2ih + gate * 128 + c * 8);
        *(uint4*)&Wsh[gate * XSW + c * 8] = v;
    }
    // stage x tile: 64 tokens x 128 ch, BN1-normalize, convert fp16
    for (int idx = tid; idx < 2048; idx += 512) {
        int tl = idx >> 5, f4 = idx & 31;
        int tok = tok0 + tl;
        float4 v = __ldg(((const float4*)g_out1) + (size_t)tok * 32 + f4);
        int in = (tok >> 7) >> 9;
        int m0 = f4 * 4;
        float2 b0 = g_bn1[in * H + m0 + 0];
        float2 b1 = g_bn1[in * H + m0 + 1];
        float2 b2 = g_bn1[in * H + m0 + 2];
        float2 b3 = g_bn1[in * H + m0 + 3];
        __half2 h01 = __floats2half2_rn(fmaf(v.x, b0.x, b0.y), fmaf(v.y, b1.x, b1.y));
        __half2 h23 = __floats2half2_rn(fmaf(v.z, b2.x, b2.y), fmaf(v.w, b3.x, b3.y));
        unsigned* dst = (unsigned*)&xsh[tl * XSW + m0];
        dst[0] = *(unsigned*)&h01;
        dst[1] = *(unsigned*)&h23;
    }
    __syncthreads();

    const int w    = tid >> 5;
    const int lane = tid & 31;
    const int mt2  = w >> 3;              // 0/1 -> tokens mt2*32..+31 (2 m-tiles)
    const int ng   = w & 7;               // gates ng*64..+63 (8 n-tiles)
    const int r4   = lane >> 2;           // 0..7
    const int c2   = (lane & 3) * 2;      // 0,2,4,6

    float d[2][8][4];
#pragma unroll
    for (int mi = 0; mi < 2; mi++)
#pragma unroll
        for (int nt = 0; nt < 8; nt++)
#pragma unroll
            for (int q = 0; q < 4; q++) d[mi][nt][q] = 0.f;

#pragma unroll
    for (int ks = 0; ks < 8; ks++) {
        int kb = ks * 16;
        unsigned a[2][4];
#pragma unroll
        for (int mi = 0; mi < 2; mi++) {
            int tb = mt2 * 32 + mi * 16;
            const __half* base = xsh + (tb + r4) * XSW + kb + c2;
            a[mi][0] = *(const unsigned*)base;
            a[mi][1] = *(const unsigned*)(base + 8 * XSW);
            a[mi][2] = *(const unsigned*)(base + 8);
            a[mi][3] = *(const unsigned*)(base + 8 * XSW + 8);
        }
#pragma unroll
        for (int nt = 0; nt < 8; nt++) {
            int gb = ng * 64 + nt * 8;
            const __half* bb = Wsh + (gb + r4) * XSW + kb + c2;
            unsigned b0 = *(const unsigned*)bb;
            unsigned b1 = *(const unsigned*)(bb + 8);
#pragma unroll
            for (int mi = 0; mi < 2; mi++)
                mma16816(d[mi][nt][0], d[mi][nt][1], d[mi][nt][2], d[mi][nt][3],
                         a[mi][0], a[mi][1], a[mi][2], a[mi][3], b0, b1);
        }
    }

    // write out: D[tok][gate] fp32
#pragma unroll
    for (int mi = 0; mi < 2; mi++) {
        int trow = tok0 + mt2 * 32 + mi * 16 + r4;
#pragma unroll
        for (int nt = 0; nt < 8; nt++) {
            int gcol = ng * 64 + nt * 8 + c2;
            *(float2*)&g_xpre[(size_t)trow * 512 + gcol]       = make_float2(d[mi][nt][0], d[mi][nt][1]);
            *(float2*)&g_xpre[(size_t)(trow + 8) * 512 + gcol] = make_float2(d[mi][nt][2], d[mi][nt][3]);
        }
    }
}

// ---------- layer 2 LSTM: recurrent part (Whh2), seed = bias + xpre ----------
__global__ void __launch_bounds__(NTH, 1)
lstm2_kernel() {
    extern __shared__ __align__(16) float smem[];
    float4* ringf4 = (float4*)smem;
    float*  hp  = smem + SM_HP;
    float*  act = smem + SM_ACT;

    const int tid = threadIdx.x;
    const int p   = tid >> 1;
    const int kh  = tid & 1;
    const int sbase = blockIdx.x * NB;

    const int myGate = p + (kh ? 256 : 0);
    const float bias = g_b2[myGate];

    const bool ktanh = kh && (p < 128);
    const float zmul = ktanh ? 2.f : 1.f;
    const float amul = ktanh ? 2.f : 1.f;
    const float aadd = ktanh ? -1.f : 0.f;
    const int  acol  = kh ? (p + 272) : p;

    const int m  = tid & 127;
    const int cm = m + ((m >> 6) << 2);
    const int sb = tid >> 7;
    float csr[3] = {0,0,0}, sum[3] = {0,0,0}, sq[3] = {0,0,0};

    for (int i = tid; i < NB * HPW; i += NTH) hp[i] = 0.f;
    __syncthreads();

    const float4* Wb = g_W2h + (kh ? (16 << 9) : 0);
    const int woff   = kh ? 512 : 0;
    const int hbase0 = kh ? HOFF : 0;
    const unsigned ring_u32 = (unsigned)__cvta_generic_to_shared(ringf4);
    const unsigned dbase = ring_u32 + (woff + p) * 16;

#pragma unroll
    for (int c = 0; c < 3; c++) {
        const float4* src = Wb + (c << 9) + p;
        unsigned dst = dbase + ((c & 3) << 14);
        cpa16(dst, src);
        cpa16(dst + 4096, src + 256);
        cpa_commit();
    }

    for (int t = 0; t < T; t++) {
        float xv[NB];
#pragma unroll
        for (int s = 0; s < NB; s++)
            xv[s] = __ldg(&g_xpre[((size_t)(sbase + s) * T + t) * 512 + myGate]);

        ull accA[NB], accB[NB];
#pragma unroll
        for (int s = 0; s < NB; s++) { accA[s] = 0ull; accB[s] = 0ull; }

#pragma unroll 4
        for (int kk = 0; kk < 16; kk++) {
            cpa_wait2();
            const float4* wsl = ringf4 + ((kk & 3) << 10) + woff + p;
            float4 wA = wsl[0];
            float4 wB = wsl[256];
            {
                int c = (kk + 3) & 15;
                const float4* src = Wb + (c << 9) + p;
                unsigned dst = dbase + ((c & 3) << 14);
                cpa16(dst, src);
                cpa16(dst + 4096, src + 256);
                cpa_commit();
            }
            ull wAlo = pk2(wA.x, wA.y), wAhi = pk2(wA.z, wA.w);
            ull wBlo = pk2(wB.x, wB.y), wBhi = pk2(wB.z, wB.w);
            const float* hrow = hp + hbase0 + 4 * kk;
#pragma unroll
            for (int s = 0; s < NB; s++) {
                ulonglong2 hv = *(const ulonglong2*)&hrow[s * HPW];
                accA[s] = ffma2(wAlo, hv.x, accA[s]);
                accA[s] = ffma2(wAhi, hv.y, accA[s]);
                accB[s] = ffma2(wBlo, hv.x, accB[s]);
                accB[s] = ffma2(wBhi, hv.y, accB[s]);
            }
        }

#pragma unroll
        for (int s = 0; s < NB; s++) {
            float2 vA = upk2(accA[s]); float zA = vA.x + vA.y;
            float2 vB = upk2(accB[s]); float zB = vB.x + vB.y;
            float seed = bias + xv[s];
            if (kh) zB += seed; else zA += seed;
            zA += __shfl_xor_sync(0xffffffffu, zA, 1);
            zB += __shfl_xor_sync(0xffffffffu, zB, 1);
            float z = kh ? zB : zA;
            float sg = sigm(z * zmul);
            act[s * ACTW + acol] = fmaf(sg, amul, aadd);
        }
        __syncthreads();

#pragma unroll
        for (int r = 0; r < 3; r++) {
            int s = sb + 4 * r;
            const float* arow = act + s * ACTW;
            float gi = arow[m], gf = arow[m + 128], gg = arow[m + 272], go = arow[m + 400];
            float c = fmaf(gf, csr[r], gi * gg);
            csr[r] = c;
            float th = fmaf(2.f, sigm(2.f * c), -1.f);
            float h = go * th;
            hp[s * HPW + cm] = h;
            sum[r] += h;
            sq[r] = fmaf(h, h, sq[r]);
            if (t == T - 1) g_lasth[(sbase + s) * H + m] = h;
        }
        __syncthreads();
    }
    cpa_wait0();
#pragma unroll
    for (int r = 0; r < 3; r++) {
        int idx = (sbase + sb + 4 * r) * H + m;
        g_ps2[idx] = sum[r];
        g_pq2[idx] = sq[r];
    }
}

// ---------- FC + L2 normalize ----------
__global__ void __launch_bounds__(128)
final_kernel(const float* __restrict__ fcW, const float* __restrict__ fcb, float* __restrict__ out) {
    __shared__ float xn[H];
    __shared__ float emb[H];
    __shared__ float red[128];
    int s = blockIdx.x, j = threadIdx.x;
    int in = s >> 9, b = s & 511;

    float2 bn = g_bn2[in * H + j];
    xn[j] = fmaf(g_lasth[s * H + j], bn.x, bn.y);
    __syncthreads();

    float e = fcb[j];
    const float* wrow = fcW + j * H;
#pragma unroll 4
    for (int k = 0; k < H; k++) e = fmaf(__ldg(&wrow[k]), xn[k], e);
    emb[j] = e;
    red[j] = e * e;
    __syncthreads();
    for (int off = 64; off > 0; off >>= 1) {
        if (j < off) red[j] += red[j + off];
        __syncthreads();
    }
    float norm = sqrtf(red[0]);
    float inv = 1.f / fmaxf(norm, 1e-12f);
    out[((size_t)in * B + b) * H + j] = emb[j] * inv;
}

extern "C" void kernel_launch(void* const* d_in, const int* in_sizes, int n_in,
                              void* d_out, int out_size) {
    const float* a    = (const float*)d_in[0];
    const float* p    = (const float*)d_in[1];
    const float* n    = (const float*)d_in[2];
    const float* Wih1 = (const float*)d_in[3];
    const float* Whh1 = (const float*)d_in[4];
    const float* bih1 = (const float*)d_in[5];
    const float* bhh1 = (const float*)d_in[6];
    const float* g1   = (const float*)d_in[7];
    const float* b1   = (const float*)d_in[8];
    const float* Wih2 = (const float*)d_in[9];
    const float* Whh2 = (const float*)d_in[10];
    const float* bih2 = (const float*)d_in[11];
    const float* bhh2 = (const float*)d_in[12];
    const float* g2   = (const float*)d_in[13];
    const float* b2   = (const float*)d_in[14];
    const float* fcW  = (const float*)d_in[15];
    const float* fcb  = (const float*)d_in[16];
    float* out = (float*)d_out;

    cudaFuncSetAttribute(lstm1_kernel, cudaFuncAttributeMaxDynamicSharedMemorySize, SMEM_BYTES);
    cudaFuncSetAttribute(lstm2_kernel, cudaFuncAttributeMaxDynamicSharedMemorySize, SMEM_BYTES);
    cudaFuncSetAttribute(xpre_kernel,  cudaFuncAttributeMaxDynamicSharedMemorySize, XP_SMEM_BYTES);

    float2 *bn1p, *bn2p;
    cudaGetSymbolAddress((void**)&bn1p, g_bn1);
    cudaGetSymbolAddress((void**)&bn2p, g_bn2);
    float *ps1, *pq1, *ps2, *pq2;
    cudaGetSymbolAddress((void**)&ps1, g_ps1);
    cudaGetSymbolAddress((void**)&pq1, g_pq1);
    cudaGetSymbolAddress((void**)&ps2, g_ps2);
    cudaGetSymbolAddress((void**)&pq2, g_pq2);

    prep_kernel<<<64, 256>>>(Wih1, Whh1, bih1, bhh1, Wih2, Whh2, bih2, bhh2);
    lstm1_kernel<<<NBLK, NTH, SMEM_BYTES>>>(a, p, n);
    bn_reduce_kernel<<<3 * H, 128>>>(ps1, pq1, g1, b1, bn1p);
    xpre_kernel<<<(S * T) / 64, 512, XP_SMEM_BYTES>>>();
    lstm2_kernel<<<NBLK, NTH, SMEM_BYTES>>>();
    bn_reduce_kernel<<<3 * H, 128>>>(ps2, pq2, g2, b2, bn2p);
    final_kernel<<<S, 128>>>(fcW, fcb, out);
}

// round 14
// speedup vs baseline: 4.5811x; 2.3099x over previous
#include <cuda_runtime.h>
#include <cuda_fp16.h>
#include <math.h>
#include <stdint.h>

constexpr int H    = 128;
constexpr int B    = 512;
constexpr int T    = 128;
constexpr int S    = 1536;   // 3 inputs * B
constexpr int NB2  = 16;     // seqs per lstm block (one mma m-tile)
constexpr int NBLK2= 96;     // S / NB2

// lstm smem strides (halves); chosen so r4-row LDS are bank-conflict-free
constexpr int WST1 = 168;    // layer1: cols 0..127 h/Whh, 128..143 x/Wih1, 144..167 zero pad
constexpr int NK1  = 9;      // 144 / 16
constexpr int WST2 = 136;    // layer2: cols 0..127, 128..135 zero pad
constexpr int NK2  = 8;
constexpr int ACT2W = 524;   // act row stride (floats)

constexpr int SMEM1_BYTES = (512 + 16) * WST1 * 2 + 16 * ACT2W * 4;  // ~206 KB
constexpr int SMEM2_BYTES = (512 + 16) * WST2 * 2 + 16 * ACT2W * 4;  // ~173 KB

// xpre mma smem: W (512 x 136 halves) + x (64 x 136 halves)
constexpr int XSW = 136;
constexpr int XP_W_HALFS = 512 * XSW;
constexpr int XP_SMEM_BYTES = (XP_W_HALFS + 64 * XSW) * 2;

// fp16 packed weights (row-major [gate][k])
__device__ __half g_Whh1_16[512 * 128];
__device__ __half g_Whh2_16[512 * 128];
__device__ __half g_Wih1_16[512 * 16];     // cols 0..4 = Wih1, rest 0
__device__ __half g_W2ih[512 * 128];       // Wih2 fp16 (for xpre)
__device__ float  g_b1[512];
__device__ float  g_b2[512];
__device__ float  g_out1[(size_t)S * T * H];
__device__ float  g_xpre[(size_t)S * T * 512];
__device__ float  g_lasth[S * H];
__device__ float  g_ps1[S * H];
__device__ float  g_pq1[S * H];
__device__ float  g_ps2[S * H];
__device__ float  g_pq2[S * H];
__device__ float2 g_bn1[3 * H];
__device__ float2 g_bn2[3 * H];

__device__ __forceinline__ float sigm(float x) {
    return __fdividef(1.f, 1.f + __expf(-x));
}
__device__ __forceinline__ void mma16816(float& d0, float& d1, float& d2, float& d3,
                                         unsigned a0, unsigned a1, unsigned a2, unsigned a3,
                                         unsigned b0, unsigned b1) {
    asm volatile("mma.sync.aligned.m16n8k16.row.col.f32.f16.f16.f32 "
                 "{%0,%1,%2,%3}, {%4,%5,%6,%7}, {%8,%9}, {%0,%1,%2,%3};"
                 : "+f"(d0), "+f"(d1), "+f"(d2), "+f"(d3)
                 : "r"(a0), "r"(a1), "r"(a2), "r"(a3), "r"(b0), "r"(b1));
}
__device__ __forceinline__ unsigned ldh2(const __half* p) { return *(const unsigned*)p; }

// ---------- pack weights ----------
__global__ void prep_kernel(const float* Wih1, const float* Whh1, const float* bih1, const float* bhh1,
                            const float* Wih2, const float* Whh2, const float* bih2, const float* bhh2) {
    int tid = blockIdx.x * blockDim.x + threadIdx.x;
    int stride = gridDim.x * blockDim.x;
    for (int idx = tid; idx < 512 * 128; idx += stride) {
        g_Whh1_16[idx] = __float2half(Whh1[idx]);
        g_Whh2_16[idx] = __float2half(Whh2[idx]);
        g_W2ih[idx]    = __float2half(Wih2[idx]);
    }
    for (int idx = tid; idx < 512 * 16; idx += stride) {
        int g = idx >> 4, d = idx & 15;
        g_Wih1_16[idx] = __float2half(d < 5 ? Wih1[g * 5 + d] : 0.f);
    }
    for (int j = tid; j < 512; j += stride) {
        g_b1[j] = bih1[j] + bhh1[j];
        g_b2[j] = bih2[j] + bhh2[j];
    }
}

// ---------- layer 1 LSTM via HMMA: 96 blocks x 512 thr, 16 seqs/block ----------
__global__ void __launch_bounds__(512, 1)
lstm1_kernel(const float* __restrict__ xa, const float* __restrict__ xp, const float* __restrict__ xn) {
    extern __shared__ __align__(16) __half hsm[];
    __half* Wsh = hsm;                        // [512][WST1]
    __half* ash = hsm + 512 * WST1;           // [16][WST1]: h cols 0..127, x cols 128..143
    float*  act = (float*)(hsm + (512 + 16) * WST1);   // [16][ACT2W]

    const int tid  = threadIdx.x;
    const int w    = tid >> 5;
    const int lane = tid & 31;
    const int r4   = lane >> 2;
    const int c2   = (lane & 3) * 2;
    const int sbase = blockIdx.x * NB2;

    // stage Wsh: 512 rows x 21 uint4 (168 halves)
    for (int idx = tid; idx < 512 * 21; idx += 512) {
        int row = idx / 21, c = idx - row * 21;
        uint4 v = make_uint4(0, 0, 0, 0);
        if (c < 16)       v = *(const uint4*)(g_Whh1_16 + row * 128 + c * 8);
        else if (c < 18)  v = *(const uint4*)(g_Wih1_16 + row * 16 + (c - 16) * 8);
        *(uint4*)&Wsh[row * WST1 + c * 8] = v;
    }
    // zero ash
    for (int idx = tid; idx < 16 * 21; idx += 512)
        *(uint4*)&ash[(idx / 21) * WST1 + (idx % 21) * 8] = make_uint4(0, 0, 0, 0);

    // bias regs for owned gates
    float2 bs[4];
#pragma unroll
    for (int nt = 0; nt < 4; nt++) bs[nt] = *(const float2*)&g_b1[w * 32 + nt * 8 + c2];
    const int gt = w >> 2;

    // phase-2 mapping: r -> tok = (tid>>7) + 4r, m = tid&127
    const int m  = tid & 127;
    const int tb = tid >> 7;
    float csr[4] = {0,0,0,0}, sum[4] = {0,0,0,0}, sq[4] = {0,0,0,0};

    // x loaders (threads 0..79)
    const float* xptr = xa; int xoff = 0, xsl = 0, xd = 0;
    const bool is_loader = (tid < NB2 * 5);
    if (is_loader) {
        xsl = tid / 5; xd = tid - 5 * xsl;
        int s = sbase + xsl, in = s >> 9, b = s & 511;
        xptr = (in == 0) ? xa : ((in == 1) ? xp : xn);
        xoff = b * (T * 5) + xd;
    }
    if (is_loader) {} // pointer setup only
    __syncthreads();
    if (is_loader) ash[xsl * WST1 + 128 + xd] = __float2half(__ldg(&xptr[xoff]));
    __syncthreads();

    for (int t = 0; t < T; t++) {
        float xnv = 0.f;
        if (is_loader && t + 1 < T) xnv = __ldg(&xptr[xoff + (t + 1) * 5]);

        float d[4][4];
#pragma unroll
        for (int nt = 0; nt < 4; nt++)
#pragma unroll
            for (int q = 0; q < 4; q++) d[nt][q] = 0.f;

#pragma unroll
        for (int ks = 0; ks < NK1; ks++) {
            int kb = ks * 16;
            const __half* ab = ash + r4 * WST1 + kb + c2;
            unsigned a0 = ldh2(ab);
            unsigned a1 = ldh2(ab + 8 * WST1);
            unsigned a2 = ldh2(ab + 8);
            unsigned a3 = ldh2(ab + 8 * WST1 + 8);
#pragma unroll
            for (int nt = 0; nt < 4; nt++) {
                const __half* bb = Wsh + (w * 32 + nt * 8 + r4) * WST1 + kb + c2;
                mma16816(d[nt][0], d[nt][1], d[nt][2], d[nt][3],
                         a0, a1, a2, a3, ldh2(bb), ldh2(bb + 8));
            }
        }

        // activation (warp-uniform gate type)
#pragma unroll
        for (int nt = 0; nt < 4; nt++) {
            float z0 = d[nt][0] + bs[nt].x, z1 = d[nt][1] + bs[nt].y;
            float z2 = d[nt][2] + bs[nt].x, z3 = d[nt][3] + bs[nt].y;
            float a0v, a1v, a2v, a3v;
            if (gt == 2) {
                a0v = fmaf(2.f, sigm(2.f * z0), -1.f);
                a1v = fmaf(2.f, sigm(2.f * z1), -1.f);
                a2v = fmaf(2.f, sigm(2.f * z2), -1.f);
                a3v = fmaf(2.f, sigm(2.f * z3), -1.f);
            } else {
                a0v = sigm(z0); a1v = sigm(z1); a2v = sigm(z2); a3v = sigm(z3);
            }
            int gcol = w * 32 + nt * 8 + c2;
            *(float2*)&act[r4 * ACT2W + gcol]       = make_float2(a0v, a1v);
            *(float2*)&act[(r4 + 8) * ACT2W + gcol] = make_float2(a2v, a3v);
        }
        __syncthreads();

        // phase 2
        if (is_loader && t + 1 < T) ash[xsl * WST1 + 128 + xd] = __float2half(xnv);
#pragma unroll
        for (int r = 0; r < 4; r++) {
            int tok = tb + 4 * r;
            const float* arow = act + tok * ACT2W;
            float gi = arow[m], gf = arow[m + 128], gg = arow[m + 256], go = arow[m + 384];
            float c = fmaf(gf, csr[r], gi * gg);
            csr[r] = c;
            float th = fmaf(2.f, sigm(2.f * c), -1.f);
            float h = go * th;
            ash[tok * WST1 + m] = __float2half(h);
            g_out1[((size_t)(sbase + tok) * T + t) * H + m] = h;
            sum[r] += h;
            sq[r] = fmaf(h, h, sq[r]);
        }
        __syncthreads();
    }
#pragma unroll
    for (int r = 0; r < 4; r++) {
        int idx = (sbase + tb + 4 * r) * H + m;
        g_ps1[idx] = sum[r];
        g_pq1[idx] = sq[r];
    }
}

// ---------- BN stats reduce (fp64 tree, deterministic) ----------
__global__ void __launch_bounds__(128)
bn_reduce_kernel(const float* __restrict__ ps, const float* __restrict__ pq,
                 const float* __restrict__ gamma, const float* __restrict__ beta,
                 float2* __restrict__ bnout) {
    __shared__ double rs[128], rq[128];
    int cidx = blockIdx.x;
    int in = cidx >> 7, c = cidx & 127;
    int t = threadIdx.x;
    double s = 0.0, q = 0.0;
    for (int b = t; b < B; b += 128) {
        int idx = (in * B + b) * H + c;
        s += (double)ps[idx];
        q += (double)pq[idx];
    }
    rs[t] = s; rq[t] = q;
    __syncthreads();
    for (int off = 64; off > 0; off >>= 1) {
        if (t < off) { rs[t] += rs[t + off]; rq[t] += rq[t + off]; }
        __syncthreads();
    }
    if (t == 0) {
        double n = (double)B * T;
        double mean = rs[0] / n;
        double var = rq[0] / n - mean * mean;
        float scale = gamma[c] * (float)rsqrt(var + 1e-5);
        float shift = beta[c] - (float)mean * scale;
        bnout[cidx] = make_float2(scale, shift);
    }
}

// ---------- xpre GEMM via HMMA: 64 tokens x 512 gates per block (R13 verified) ----------
__global__ void __launch_bounds__(512)
xpre_kernel() {
    extern __shared__ __align__(16) __half xsm[];
    __half* Wsh = xsm;                    // [512][XSW]
    __half* xsh = xsm + XP_W_HALFS;       // [64][XSW]

    const int tid  = threadIdx.x;
    const int tok0 = blockIdx.x * 64;

    for (int idx = tid; idx < 512 * 16; idx += 512) {
        int gate = idx >> 4, c = idx & 15;
        uint4 v = *(const uint4*)(g_W2ih + gate * 128 + c * 8);
        *(uint4*)&Wsh[gate * XSW + c * 8] = v;
    }
    for (int idx = tid; idx < 2048; idx += 512) {
        int tl = idx >> 5, f4 = idx & 31;
        int tok = tok0 + tl;
        float4 v = __ldg(((const float4*)g_out1) + (size_t)tok * 32 + f4);
        int in = (tok >> 7) >> 9;
        int m0 = f4 * 4;
        float2 b0 = g_bn1[in * H + m0 + 0];
        float2 b1 = g_bn1[in * H + m0 + 1];
        float2 b2 = g_bn1[in * H + m0 + 2];
        float2 b3 = g_bn1[in * H + m0 + 3];
        __half2 h01 = __floats2half2_rn(fmaf(v.x, b0.x, b0.y), fmaf(v.y, b1.x, b1.y));
        __half2 h23 = __floats2half2_rn(fmaf(v.z, b2.x, b2.y), fmaf(v.w, b3.x, b3.y));
        unsigned* dst = (unsigned*)&xsh[tl * XSW + m0];
        dst[0] = *(unsigned*)&h01;
        dst[1] = *(unsigned*)&h23;
    }
    __syncthreads();

    const int w    = tid >> 5;
    const int lane = tid & 31;
    const int mt2  = w >> 3;
    const int ng   = w & 7;
    const int r4   = lane >> 2;
    const int c2   = (lane & 3) * 2;

    float d[2][8][4];
#pragma unroll
    for (int mi = 0; mi < 2; mi++)
#pragma unroll
        for (int nt = 0; nt < 8; nt++)
#pragma unroll
            for (int q = 0; q < 4; q++) d[mi][nt][q] = 0.f;

#pragma unroll
    for (int ks = 0; ks < 8; ks++) {
        int kb = ks * 16;
        unsigned a[2][4];
#pragma unroll
        for (int mi = 0; mi < 2; mi++) {
            int tb2 = mt2 * 32 + mi * 16;
            const __half* base = xsh + (tb2 + r4) * XSW + kb + c2;
            a[mi][0] = ldh2(base);
            a[mi][1] = ldh2(base + 8 * XSW);
            a[mi][2] = ldh2(base + 8);
            a[mi][3] = ldh2(base + 8 * XSW + 8);
        }
#pragma unroll
        for (int nt = 0; nt < 8; nt++) {
            const __half* bb = Wsh + (ng * 64 + nt * 8 + r4) * XSW + kb + c2;
            unsigned b0 = ldh2(bb);
            unsigned b1 = ldh2(bb + 8);
#pragma unroll
            for (int mi = 0; mi < 2; mi++)
                mma16816(d[mi][nt][0], d[mi][nt][1], d[mi][nt][2], d[mi][nt][3],
                         a[mi][0], a[mi][1], a[mi][2], a[mi][3], b0, b1);
        }
    }
#pragma unroll
    for (int mi = 0; mi < 2; mi++) {
        int trow = tok0 + mt2 * 32 + mi * 16 + r4;
#pragma unroll
        for (int nt = 0; nt < 8; nt++) {
            int gcol = ng * 64 + nt * 8 + c2;
            *(float2*)&g_xpre[(size_t)trow * 512 + gcol]       = make_float2(d[mi][nt][0], d[mi][nt][1]);
            *(float2*)&g_xpre[(size_t)(trow + 8) * 512 + gcol] = make_float2(d[mi][nt][2], d[mi][nt][3]);
        }
    }
}

// ---------- layer 2 LSTM via HMMA: seed = bias + xpre ----------
__global__ void __launch_bounds__(512, 1)
lstm2_kernel() {
    extern __shared__ __align__(16) __half hsm[];
    __half* Wsh = hsm;                        // [512][WST2]
    __half* ash = hsm + 512 * WST2;           // [16][WST2]
    float*  act = (float*)(hsm + (512 + 16) * WST2);

    const int tid  = threadIdx.x;
    const int w    = tid >> 5;
    const int lane = tid & 31;
    const int r4   = lane >> 2;
    const int c2   = (lane & 3) * 2;
    const int sbase = blockIdx.x * NB2;

    for (int idx = tid; idx < 512 * 17; idx += 512) {
        int row = idx / 17, c = idx - row * 17;
        uint4 v = make_uint4(0, 0, 0, 0);
        if (c < 16) v = *(const uint4*)(g_Whh2_16 + row * 128 + c * 8);
        *(uint4*)&Wsh[row * WST2 + c * 8] = v;
    }
    for (int idx = tid; idx < 16 * 17; idx += 512)
        *(uint4*)&ash[(idx / 17) * WST2 + (idx % 17) * 8] = make_uint4(0, 0, 0, 0);

    float2 bs[4];
#pragma unroll
    for (int nt = 0; nt < 4; nt++) bs[nt] = *(const float2*)&g_b2[w * 32 + nt * 8 + c2];
    const int gt = w >> 2;

    const int m  = tid & 127;
    const int tb = tid >> 7;
    float csr[4] = {0,0,0,0}, sum[4] = {0,0,0,0}, sq[4] = {0,0,0,0};
    __syncthreads();

    for (int t = 0; t < T; t++) {
        // seed loads (latency hidden under mma)
        float2 sd0[4], sd1[4];
        {
            size_t rowA = ((size_t)(sbase + r4) * T + t) * 512;
            size_t rowB = ((size_t)(sbase + r4 + 8) * T + t) * 512;
#pragma unroll
            for (int nt = 0; nt < 4; nt++) {
                int gcol = w * 32 + nt * 8 + c2;
                sd0[nt] = *(const float2*)&g_xpre[rowA + gcol];
                sd1[nt] = *(const float2*)&g_xpre[rowB + gcol];
            }
        }

        float d[4][4];
#pragma unroll
        for (int nt = 0; nt < 4; nt++)
#pragma unroll
            for (int q = 0; q < 4; q++) d[nt][q] = 0.f;

#pragma unroll
        for (int ks = 0; ks < NK2; ks++) {
            int kb = ks * 16;
            const __half* ab = ash + r4 * WST2 + kb + c2;
            unsigned a0 = ldh2(ab);
            unsigned a1 = ldh2(ab + 8 * WST2);
            unsigned a2 = ldh2(ab + 8);
            unsigned a3 = ldh2(ab + 8 * WST2 + 8);
#pragma unroll
            for (int nt = 0; nt < 4; nt++) {
                const __half* bb = Wsh + (w * 32 + nt * 8 + r4) * WST2 + kb + c2;
                mma16816(d[nt][0], d[nt][1], d[nt][2], d[nt][3],
                         a0, a1, a2, a3, ldh2(bb), ldh2(bb + 8));
            }
        }

#pragma unroll
        for (int nt = 0; nt < 4; nt++) {
            float z0 = d[nt][0] + bs[nt].x + sd0[nt].x;
            float z1 = d[nt][1] + bs[nt].y + sd0[nt].y;
            float z2 = d[nt][2] + bs[nt].x + sd1[nt].x;
            float z3 = d[nt][3] + bs[nt].y + sd1[nt].y;
            float a0v, a1v, a2v, a3v;
            if (gt == 2) {
                a0v = fmaf(2.f, sigm(2.f * z0), -1.f);
                a1v = fmaf(2.f, sigm(2.f * z1), -1.f);
                a2v = fmaf(2.f, sigm(2.f * z2), -1.f);
                a3v = fmaf(2.f, sigm(2.f * z3), -1.f);
            } else {
                a0v = sigm(z0); a1v = sigm(z1); a2v = sigm(z2); a3v = sigm(z3);
            }
            int gcol = w * 32 + nt * 8 + c2;
            *(float2*)&act[r4 * ACT2W + gcol]       = make_float2(a0v, a1v);
            *(float2*)&act[(r4 + 8) * ACT2W + gcol] = make_float2(a2v, a3v);
        }
        __syncthreads();

#pragma unroll
        for (int r = 0; r < 4; r++) {
            int tok = tb + 4 * r;
            const float* arow = act + tok * ACT2W;
            float gi = arow[m], gf = arow[m + 128], gg = arow[m + 256], go = arow[m + 384];
            float c = fmaf(gf, csr[r], gi * gg);
            csr[r] = c;
            float th = fmaf(2.f, sigm(2.f * c), -1.f);
            float h = go * th;
            ash[tok * WST2 + m] = __float2half(h);
            sum[r] += h;
            sq[r] = fmaf(h, h, sq[r]);
            if (t == T - 1) g_lasth[(sbase + tok) * H + m] = h;
        }
        __syncthreads();
    }
#pragma unroll
    for (int r = 0; r < 4; r++) {
        int idx = (sbase + tb + 4 * r) * H + m;
        g_ps2[idx] = sum[r];
        g_pq2[idx] = sq[r];
    }
}

// ---------- FC + L2 normalize ----------
__global__ void __launch_bounds__(128)
final_kernel(const float* __restrict__ fcW, const float* __restrict__ fcb, float* __restrict__ out) {
    __shared__ float xn[H];
    __shared__ float emb[H];
    __shared__ float red[128];
    int s = blockIdx.x, j = threadIdx.x;
    int in = s >> 9, b = s & 511;

    float2 bn = g_bn2[in * H + j];
    xn[j] = fmaf(g_lasth[s * H + j], bn.x, bn.y);
    __syncthreads();

    float e = fcb[j];
    const float* wrow = fcW + j * H;
#pragma unroll 4
    for (int k = 0; k < H; k++) e = fmaf(__ldg(&wrow[k]), xn[k], e);
    emb[j] = e;
    red[j] = e * e;
    __syncthreads();
    for (int off = 64; off > 0; off >>= 1) {
        if (j < off) red[j] += red[j + off];
        __syncthreads();
    }
    float norm = sqrtf(red[0]);
    float inv = 1.f / fmaxf(norm, 1e-12f);
    out[((size_t)in * B + b) * H + j] = emb[j] * inv;
}

extern "C" void kernel_launch(void* const* d_in, const int* in_sizes, int n_in,
                              void* d_out, int out_size) {
    const float* a    = (const float*)d_in[0];
    const float* p    = (const float*)d_in[1];
    const float* n    = (const float*)d_in[2];
    const float* Wih1 = (const float*)d_in[3];
    const float* Whh1 = (const float*)d_in[4];
    const float* bih1 = (const float*)d_in[5];
    const float* bhh1 = (const float*)d_in[6];
    const float* g1   = (const float*)d_in[7];
    const float* b1   = (const float*)d_in[8];
    const float* Wih2 = (const float*)d_in[9];
    const float* Whh2 = (const float*)d_in[10];
    const float* bih2 = (const float*)d_in[11];
    const float* bhh2 = (const float*)d_in[12];
    const float* g2   = (const float*)d_in[13];
    const float* b2   = (const float*)d_in[14];
    const float* fcW  = (const float*)d_in[15];
    const float* fcb  = (const float*)d_in[16];
    float* out = (float*)d_out;

    cudaFuncSetAttribute(lstm1_kernel, cudaFuncAttributeMaxDynamicSharedMemorySize, SMEM1_BYTES);
    cudaFuncSetAttribute(lstm2_kernel, cudaFuncAttributeMaxDynamicSharedMemorySize, SMEM2_BYTES);
    cudaFuncSetAttribute(xpre_kernel,  cudaFuncAttributeMaxDynamicSharedMemorySize, XP_SMEM_BYTES);

    float2 *bn1p, *bn2p;
    cudaGetSymbolAddress((void**)&bn1p, g_bn1);
    cudaGetSymbolAddress((void**)&bn2p, g_bn2);
    float *ps1, *pq1, *ps2, *pq2;
    cudaGetSymbolAddress((void**)&ps1, g_ps1);
    cudaGetSymbolAddress((void**)&pq1, g_pq1);
    cudaGetSymbolAddress((void**)&ps2, g_ps2);
    cudaGetSymbolAddress((void**)&pq2, g_pq2);

    prep_kernel<<<128, 256>>>(Wih1, Whh1, bih1, bhh1, Wih2, Whh2, bih2, bhh2);
    lstm1_kernel<<<NBLK2, 512, SMEM1_BYTES>>>(a, p, n);
    bn_reduce_kernel<<<3 * H, 128>>>(ps1, pq1, g1, b1, bn1p);
    xpre_kernel<<<(S * T) / 64, 512, XP_SMEM_BYTES>>>();
    lstm2_kernel<<<NBLK2, 512, SMEM2_BYTES>>>();
    bn_reduce_kernel<<<3 * H, 128>>>(ps2, pq2, g2, b2, bn2p);
    final_kernel<<<S, 128>>>(fcW, fcb, out);
}